// round 11
// baseline (speedup 1.0000x reference)
#include <cuda_runtime.h>
#include <cuda_fp16.h>
#include <cstdint>
#include <cstddef>

#define BB 4
#define NQ 16384
#define MP 4096
#define C1V 128
#define C2V 256
#define D0 256
#define D1 128
#define NTOT (BB*NQ)   // 65536
#define GC 32          // cells per axis
#define NCELL (GC*GC*GC)

// ---------------- scratch (device globals; no allocation allowed) ----------------
__device__ float4 g_xyz2p[BB*MP];                  // packed xyz2 + norm
__device__ float  g_sc0[D0], g_sh0[D0], g_sc1[D1], g_sh1[D1];
__device__ float  g_wgt[NTOT*3];
__device__ int    g_idx[NTOT*3];
__device__ int    g_cnt[BB*NCELL];                 // per-cell point counts
__device__ int2   g_cellSC[BB*NCELL];              // per-cell (start, count)
__device__ int    g_pcell[BB*MP], g_pslot[BB*MP];
__device__ float4 g_sortP[BB*MP];                  // cell-sorted points (+norm)
__device__ int    g_sortI[BB*MP];                  // original in-batch index
__device__ __half g_A1h[(size_t)NTOT*C1V];         // points1 fp16 (16 MB)
__device__ __half g_A2h[BB*MP*C2V];                // points2 fp16 (8 MB)
__device__ __half g_W0a[256*256];                  // w0[0:256,:]^T  (K-major fp16)
__device__ __half g_W0b[256*128];                  // w0[256:384,:]^T
__device__ __half g_W1h[128*256];                  // w1^T
__device__ float  g_P2W[BB*MP*D0];                 // points2 @ w0a (16 MB, fp32)
__device__ __half g_G1h[(size_t)NTOT*D0];          // gathered first-layer partial fp16
__device__ __half g_Hh[(size_t)NTOT*D0];           // layer-1 activations fp16

// ---------------- PTX helpers ----------------
__device__ __forceinline__ uint32_t smem_u32(const void* p){
    uint32_t a;
    asm("{ .reg .u64 t; cvta.to.shared.u64 t, %1; cvt.u32.u64 %0, t; }" : "=r"(a) : "l"(p));
    return a;
}
__device__ __forceinline__ void cpa(uint32_t dst, const void* src){
    asm volatile("cp.async.ca.shared.global [%0], [%1], 16;" :: "r"(dst), "l"(src) : "memory");
}
__device__ __forceinline__ void cp_commit(){ asm volatile("cp.async.commit_group;" ::: "memory"); }
template<int NN> __device__ __forceinline__ void cp_wait(){ asm volatile("cp.async.wait_group %0;" :: "n"(NN) : "memory"); }

__device__ __forceinline__ void ldsm4(uint32_t& r0, uint32_t& r1, uint32_t& r2, uint32_t& r3, uint32_t addr){
    asm volatile("ldmatrix.sync.aligned.m8n8.x4.shared.b16 {%0,%1,%2,%3}, [%4];"
        : "=r"(r0), "=r"(r1), "=r"(r2), "=r"(r3) : "r"(addr));
}
__device__ __forceinline__ void mma16816(float* c, const uint32_t* a, const uint32_t* b){
    asm volatile(
        "mma.sync.aligned.m16n8k16.row.col.f32.f16.f16.f32 "
        "{%0,%1,%2,%3}, {%4,%5,%6,%7}, {%8,%9}, {%0,%1,%2,%3};"
        : "+f"(c[0]), "+f"(c[1]), "+f"(c[2]), "+f"(c[3])
        : "r"(a[0]), "r"(a[1]), "r"(a[2]), "r"(a[3]), "r"(b[0]), "r"(b[1]));
}

__device__ __forceinline__ int cellc(float v){
    int c = (int)floorf((v + 4.0f) * 4.0f);
    return min(max(c, 0), GC-1);
}

// ---------------- prep: pack xyz2 (+norm), zero counts, BN scale/shift ----------------
__global__ void prep_kernel(const float* __restrict__ xyz2,
                            const float* __restrict__ G0, const float* __restrict__ B0,
                            const float* __restrict__ M0, const float* __restrict__ V0,
                            const float* __restrict__ G1, const float* __restrict__ B1,
                            const float* __restrict__ M1, const float* __restrict__ V1)
{
    int i = blockIdx.x*256 + threadIdx.x;        // grid 512 -> 131072 threads
    if (i < BB*NCELL) g_cnt[i] = 0;
    if (i < BB*MP){
        float x = xyz2[i*3+0], y = xyz2[i*3+1], z = xyz2[i*3+2];
        g_xyz2p[i] = make_float4(x, y, z, x*x + y*y + z*z);
    }
    if (blockIdx.x == 0){
        int t = threadIdx.x;
        if (t < D0){ float s = G0[t]*rsqrtf(V0[t]+1e-3f); g_sc0[t]=s; g_sh0[t]=B0[t]-M0[t]*s; }
        if (t < D1){ float s = G1[t]*rsqrtf(V1[t]+1e-3f); g_sc1[t]=s; g_sh1[t]=B1[t]-M1[t]*s; }
    }
}

// ---------------- bin: cell id + slot per point ----------------
__global__ void __launch_bounds__(256) bin_kernel(const float* __restrict__ xyz2)
{
    int p = blockIdx.x*256 + threadIdx.x;        // grid 64 -> 16384
    float x = xyz2[p*3+0], y = xyz2[p*3+1], z = xyz2[p*3+2];
    int b = p >> 12;
    int cell = (cellc(z) << 10) | (cellc(y) << 5) | cellc(x);
    g_pcell[p] = cell;
    g_pslot[p] = atomicAdd(&g_cnt[(b << 15) + cell], 1);
}

// ---------------- scan (per batch, 1 block) + scatter ----------------
__global__ void __launch_bounds__(1024) scan_scatter_kernel()
{
    __shared__ int part[1024];
    const int b = blockIdx.x, t = threadIdx.x;
    const int* cnt = g_cnt + (b << 15);
    int2* sc = g_cellSC + (b << 15);

    int loc[32];
    int s = 0;
    const int base = t*32;
    #pragma unroll
    for (int k = 0; k < 32; ++k){ loc[k] = s; s += cnt[base+k]; }
    part[t] = s;
    __syncthreads();
    const int mysum = s;
    for (int off = 1; off < 1024; off <<= 1){
        int v = (t >= off) ? part[t-off] : 0;
        __syncthreads();
        part[t] += v;
        __syncthreads();
    }
    const int excl = part[t] - mysum;
    #pragma unroll
    for (int k = 0; k < 32; ++k)
        sc[base+k] = make_int2(excl + loc[k], cnt[base+k]);
    __syncthreads();

    // scatter the batch's 4096 points into cell-sorted order
    for (int i = t; i < MP; i += 1024){
        int p = (b << 12) + i;
        int dst = sc[g_pcell[p]].x + g_pslot[p];
        g_sortP[(b << 12) + dst] = g_xyz2p[p];
        g_sortI[(b << 12) + dst] = i;
    }
}

// ---------------- search: expanding-shell exact 3-NN + weights ----------------
__global__ void __launch_bounds__(128) search_kernel(const float* __restrict__ xyz1)
{
    const int q = blockIdx.x*128 + threadIdx.x;  // grid 512
    const int b = q >> 14;
    const float x = xyz1[q*3+0], y = xyz1[q*3+1], z = xyz1[q*3+2];
    const float n1 = x*x + y*y + z*z;
    const float ax = -2.f*x, ay = -2.f*y, az = -2.f*z;
    const int cx = cellc(x), cy = cellc(y), cz = cellc(z);

    const float4* SP = g_sortP + (b << 12);
    const int*    SI = g_sortI + (b << 12);
    const int2*   SC = g_cellSC + (b << 15);

    float d0v = 3.0e37f, d1v = 3.0e37f, d2v = 3.0e37f;
    int   i0 = 0, i1 = 0, i2 = 0;

    for (int r = 0; r < GC; ++r){
        const int xlo = max(cx-r, 0), xhi = min(cx+r, GC-1);
        const int ylo = max(cy-r, 0), yhi = min(cy+r, GC-1);
        const int zlo = max(cz-r, 0), zhi = min(cz+r, GC-1);
        for (int iz = zlo; iz <= zhi; ++iz){
            const int mz = abs(iz - cz);
            for (int iy = ylo; iy <= yhi; ++iy){
                const int mzy = max(mz, abs(iy - cy));
                for (int ix = xlo; ix <= xhi; ++ix){
                    if (max(mzy, abs(ix - cx)) != r) continue;   // shell only
                    int2 scv = SC[(iz << 10) | (iy << 5) | ix];
                    const int e = scv.x + scv.y;
                    for (int j = scv.x; j < e; ++j){
                        float4 t = SP[j];
                        float d = fmaf(az, t.z, fmaf(ay, t.y, fmaf(ax, t.x, t.w))) + n1;
                        if (d <= d2v){
                            int pi = SI[j];
                            if (d < d2v || pi < i2){
                                if (d < d1v || (d == d1v && pi < i1)){
                                    d2v = d1v; i2 = i1;
                                    if (d < d0v || (d == d0v && pi < i0)){
                                        d1v = d0v; i1 = i0; d0v = d; i0 = pi;
                                    } else { d1v = d; i1 = pi; }
                                } else { d2v = d; i2 = pi; }
                            }
                        }
                    }
                }
            }
        }
        // stopping rule: nearest possible unvisited point
        float f = 3.0e37f;
        if (cx-r > 0)    f = fminf(f, x - (-4.f + 0.25f*(float)(cx-r)));
        if (cx+r < GC-1) f = fminf(f, (-4.f + 0.25f*(float)(cx+r+1)) - x);
        if (cy-r > 0)    f = fminf(f, y - (-4.f + 0.25f*(float)(cy-r)));
        if (cy+r < GC-1) f = fminf(f, (-4.f + 0.25f*(float)(cy+r+1)) - y);
        if (cz-r > 0)    f = fminf(f, z - (-4.f + 0.25f*(float)(cz-r)));
        if (cz+r < GC-1) f = fminf(f, (-4.f + 0.25f*(float)(cz+r+1)) - z);
        if (d2v <= f*f*0.9998f) break;
    }

    float e0 = fmaxf(d0v, 1e-10f);
    float e1 = fmaxf(d1v, 1e-10f);
    float e2 = fmaxf(d2v, 1e-10f);
    float w0 = 1.f/e0, w1 = 1.f/e1, w2 = 1.f/e2;
    float inv = 1.f/(w0 + w1 + w2);
    g_wgt[q*3+0] = w0*inv; g_wgt[q*3+1] = w1*inv; g_wgt[q*3+2] = w2*inv;
    g_idx[q*3+0] = i0;     g_idx[q*3+1] = i1;     g_idx[q*3+2] = i2;
}

// ---------------- fp32 -> fp16 vector convert ----------------
__global__ void __launch_bounds__(256) f2h_kernel(const float4* __restrict__ in, __half2* __restrict__ out){
    int i = blockIdx.x*256 + threadIdx.x;
    float4 v = in[i];
    out[2*i+0] = __floats2half2_rn(v.x, v.y);
    out[2*i+1] = __floats2half2_rn(v.z, v.w);
}

// ---------------- weight transpose + fp16 (K-major for B operand) ----------------
__global__ void __launch_bounds__(256) wtrans_kernel(const float* __restrict__ w0, const float* __restrict__ w1){
    int t = blockIdx.x*256 + threadIdx.x;            // 0..131071
    if (t < 65536){
        int n = t >> 8, k = t & 255;
        g_W0a[n*256 + k] = __float2half_rn(w0[k*256 + n]);
    } else if (t < 98304){
        int u = t - 65536; int n = u >> 7, k = u & 127;
        g_W0b[n*128 + k] = __float2half_rn(w0[(256 + k)*256 + n]);
    } else {
        int u = t - 98304; int n = u >> 8, k = u & 255;
        g_W1h[n*256 + k] = __float2half_rn(w1[k*128 + n]);
    }
}

// ---------------- weighted gather of P2W rows -> fp16 first-layer partial ----------------
__global__ void __launch_bounds__(256) gather_kernel()
{
    int t = blockIdx.x*256 + threadIdx.x;
    int q = t >> 6;
    int c = t & 63;
    int b = q >> 14;
    float w0 = g_wgt[q*3+0], w1 = g_wgt[q*3+1], w2 = g_wgt[q*3+2];
    const float4* P = (const float4*)g_P2W;
    int base = b * (MP * (D0/4));
    float4 p0 = P[base + g_idx[q*3+0]*(D0/4) + c];
    float4 p1 = P[base + g_idx[q*3+1]*(D0/4) + c];
    float4 p2 = P[base + g_idx[q*3+2]*(D0/4) + c];
    float rx = w0*p0.x + w1*p1.x + w2*p2.x;
    float ry = w0*p0.y + w1*p1.y + w2*p2.y;
    float rz = w0*p0.z + w1*p1.z + w2*p2.z;
    float rw = w0*p0.w + w1*p1.w + w2*p2.w;
    __half2* o = (__half2*)g_G1h;
    o[((size_t)q*D0 >> 1) + c*2 + 0] = __floats2half2_rn(rx, ry);
    o[((size_t)q*D0 >> 1) + c*2 + 1] = __floats2half2_rn(rz, rw);
}

// ---------------- fp16 tensor-core GEMM: out = epi(A[M,K]h @ Bt[Nc,K]h^T (+G1h)) ------
template<bool GATHER, bool BN, bool OUT_HALF>
__global__ void __launch_bounds__(256) gemm_h(
    const __half* __restrict__ A, const __half* __restrict__ Bt,
    const float* __restrict__ scale, const float* __restrict__ shift,
    void* __restrict__ outv, int K, int NcOut)
{
    __shared__ __half As[2][128*40];
    __shared__ __half Bs[2][128*40];

    const int tid  = threadIdx.x;
    const int lane = tid & 31, warp = tid >> 5;
    const int wm = warp & 3, wn = warp >> 2;
    const int mBase = blockIdx.x * 128;
    const int nBase = blockIdx.y * 128;

    float acc[2][8][4];
    #pragma unroll
    for (int mt = 0; mt < 2; ++mt)
        #pragma unroll
        for (int nt = 0; nt < 8; ++nt)
            #pragma unroll
            for (int c = 0; c < 4; ++c) acc[mt][nt][c] = 0.f;

    const uint32_t sA_[2] = { smem_u32(As[0]), smem_u32(As[1]) };
    const uint32_t sB_[2] = { smem_u32(Bs[0]), smem_u32(Bs[1]) };

    const int g  = lane >> 3, lr = lane & 7;
    const uint32_t offA = (uint32_t)((wm*32 + (g&1)*8 + lr)*40 + (g>>1)*8);
    const uint32_t offB = (uint32_t)((wn*64 + (g>>1)*8 + lr)*40 + (g&1)*8);

    const int lrow = tid >> 1;
    const int lseg2 = (tid & 1) * 2;
    const __half* Ag = A + (size_t)(mBase + lrow)*K + lseg2*8;
    const __half* Bg = Bt + (size_t)(nBase + lrow)*K + lseg2*8;
    const uint32_t dA = (uint32_t)(lrow*40 + lseg2*8)*2;
    const uint32_t dB = dA;

    auto load_tile = [&](int kc, int buf){
        const __half* a = Ag + kc*32;
        const __half* b = Bg + kc*32;
        cpa(sA_[buf] + dA,      a);
        cpa(sA_[buf] + dA + 16, a + 8);
        cpa(sB_[buf] + dB,      b);
        cpa(sB_[buf] + dB + 16, b + 8);
        cp_commit();
    };

    const int KC = K >> 5;
    load_tile(0, 0);
    for (int kc = 0; kc < KC; ++kc){
        const int buf = kc & 1;
        if (kc + 1 < KC){ load_tile(kc+1, buf^1); cp_wait<1>(); }
        else            { cp_wait<0>(); }
        __syncthreads();

        const uint32_t sA = sA_[buf], sB = sB_[buf];
        #pragma unroll
        for (int ks = 0; ks < 2; ++ks){
            uint32_t af[2][4];
            uint32_t bf[8][2];
            #pragma unroll
            for (int mt = 0; mt < 2; ++mt)
                ldsm4(af[mt][0], af[mt][1], af[mt][2], af[mt][3],
                      sA + (offA + mt*16*40 + ks*16)*2);
            #pragma unroll
            for (int ntp = 0; ntp < 4; ++ntp)
                ldsm4(bf[2*ntp][0], bf[2*ntp][1], bf[2*ntp+1][0], bf[2*ntp+1][1],
                      sB + (offB + ntp*16*40 + ks*16)*2);
            #pragma unroll
            for (int mt = 0; mt < 2; ++mt)
                #pragma unroll
                for (int nt = 0; nt < 8; ++nt)
                    mma16816(acc[mt][nt], af[mt], bf[nt]);
        }
        __syncthreads();
    }

    #pragma unroll
    for (int mt = 0; mt < 2; ++mt){
        #pragma unroll
        for (int h = 0; h < 2; ++h){
            const int r = mBase + wm*32 + mt*16 + (lane >> 2) + h*8;
            const __half* g1row = GATHER ? (g_G1h + (size_t)r*D0) : nullptr;
            #pragma unroll
            for (int nt = 0; nt < 8; ++nt){
                const int c = nBase + wn*64 + nt*8 + (lane & 3)*2;
                float v0 = acc[mt][nt][h*2+0];
                float v1 = acc[mt][nt][h*2+1];
                if (GATHER){
                    float2 gg = __half22float2(*(const __half2*)(g1row + c));
                    v0 += gg.x; v1 += gg.y;
                }
                if (BN){
                    float2 sc = *(const float2*)(scale + c);
                    float2 sh = *(const float2*)(shift + c);
                    v0 = fmaxf(fmaf(v0, sc.x, sh.x), 0.f);
                    v1 = fmaxf(fmaf(v1, sc.y, sh.y), 0.f);
                }
                if (OUT_HALF){
                    __half2* o = (__half2*)outv;
                    o[((size_t)r*NcOut + c) >> 1] = __floats2half2_rn(v0, v1);
                } else {
                    float2* o = (float2*)outv;
                    o[((size_t)r*NcOut + c) >> 1] = make_float2(v0, v1);
                }
            }
        }
    }
}

// ---------------- launch ----------------
extern "C" void kernel_launch(void* const* d_in, const int* in_sizes, int n_in,
                              void* d_out, int out_size)
{
    const float* xyz1    = (const float*)d_in[0];
    const float* xyz2    = (const float*)d_in[1];
    const float* points1 = (const float*)d_in[2];
    const float* points2 = (const float*)d_in[3];
    const float* w0 = (const float*)d_in[4];
    const float* g0 = (const float*)d_in[5];
    const float* b0 = (const float*)d_in[6];
    const float* m0 = (const float*)d_in[7];
    const float* v0 = (const float*)d_in[8];
    const float* w1 = (const float*)d_in[9];
    const float* g1 = (const float*)d_in[10];
    const float* b1 = (const float*)d_in[11];
    const float* m1 = (const float*)d_in[12];
    const float* v1 = (const float*)d_in[13];
    float* out = (float*)d_out;

    void *pA1h=nullptr, *pA2h=nullptr, *pW0a=nullptr, *pW0b=nullptr, *pW1h=nullptr,
         *pP2W=nullptr, *pHh=nullptr, *pSc0=nullptr, *pSh0=nullptr, *pSc1=nullptr, *pSh1=nullptr;
    cudaGetSymbolAddress(&pA1h, g_A1h);
    cudaGetSymbolAddress(&pA2h, g_A2h);
    cudaGetSymbolAddress(&pW0a, g_W0a);
    cudaGetSymbolAddress(&pW0b, g_W0b);
    cudaGetSymbolAddress(&pW1h, g_W1h);
    cudaGetSymbolAddress(&pP2W, g_P2W);
    cudaGetSymbolAddress(&pHh,  g_Hh);
    cudaGetSymbolAddress(&pSc0, g_sc0);
    cudaGetSymbolAddress(&pSh0, g_sh0);
    cudaGetSymbolAddress(&pSc1, g_sc1);
    cudaGetSymbolAddress(&pSh1, g_sh1);

    // 1) pack xyz2 + zero cell counts + BN constants
    prep_kernel<<<512, 256>>>(xyz2, g0, b0, m0, v0, g1, b1, m1, v1);

    // 2) bin points into 32^3 grid
    bin_kernel<<<64, 256>>>(xyz2);

    // 3) per-batch prefix scan + scatter into cell-sorted order
    scan_scatter_kernel<<<4, 1024>>>();

    // 4) expanding-shell exact 3-NN search (profiled slot)
    search_kernel<<<512, 128>>>(xyz1);

    // 5-6) fp16 conversions of activations
    f2h_kernel<<<NTOT*C1V/4/256, 256>>>((const float4*)points1, (__half2*)pA1h);
    f2h_kernel<<<BB*MP*C2V/4/256, 256>>>((const float4*)points2, (__half2*)pA2h);

    // 7) weight transpose + fp16
    wtrans_kernel<<<512, 256>>>(w0, w1);

    // 8) P2W = points2 @ w0[0:256,:]   (M=16384, K=256, N=256) -> fp32
    gemm_h<false,false,false><<<dim3(128, 2), 256>>>(
        (const __half*)pA2h, (const __half*)pW0a, nullptr, nullptr, pP2W, 256, 256);

    // 9) G1h = weighted gather of P2W rows -> fp16
    gather_kernel<<<16384, 256>>>();

    // 10) H = relu(bn0(points1 @ w0[256:384,:] + G1h)) -> fp16
    gemm_h<true,true,true><<<dim3(512, 2), 256>>>(
        (const __half*)pA1h, (const __half*)pW0b,
        (const float*)pSc0, (const float*)pSh0, pHh, 128, 256);

    // 11) out = relu(bn1(H @ w1)) -> fp32
    gemm_h<false,true,false><<<dim3(512, 1), 256>>>(
        (const __half*)pHh, (const __half*)pW1h,
        (const float*)pSc1, (const float*)pSh1, out, 256, 128);
}

// round 12
// speedup vs baseline: 2.8859x; 2.8859x over previous
#include <cuda_runtime.h>
#include <cuda_fp16.h>
#include <cstdint>
#include <cstddef>

#define BB 4
#define NQ 16384
#define MP 4096
#define C1V 128
#define C2V 256
#define D0 256
#define D1 128
#define NTOT (BB*NQ)   // 65536
#define GC 32          // cells per axis
#define NCELL (GC*GC*GC)
#define RMAX 4

// ---------------- scratch (device globals; no allocation allowed) ----------------
__device__ float4 g_xyz2p[BB*MP];                  // packed xyz2 + norm
__device__ float  g_sc0[D0], g_sh0[D0], g_sc1[D1], g_sh1[D1];
__device__ float  g_wgt[NTOT*3];
__device__ int    g_idx[NTOT*3];
__device__ int    g_cnt[BB*NCELL];                 // per-cell point counts
__device__ int2   g_cellSC[BB*NCELL];              // per-cell (start, count)
__device__ int    g_pcell[BB*MP], g_pslot[BB*MP];
__device__ float4 g_sortP[BB*MP];                  // cell-sorted points (+norm)
__device__ int    g_sortI[BB*MP];                  // original in-batch index
__device__ int    g_fbCnt;                         // fallback query count
__device__ int    g_fbList[NTOT];                  // fallback query ids
__device__ __half g_A1h[(size_t)NTOT*C1V];
__device__ __half g_A2h[BB*MP*C2V];
__device__ __half g_W0a[256*256];
__device__ __half g_W0b[256*128];
__device__ __half g_W1h[128*256];
__device__ float  g_P2W[BB*MP*D0];
__device__ __half g_G1h[(size_t)NTOT*D0];
__device__ __half g_Hh[(size_t)NTOT*D0];

// ---------------- PTX helpers ----------------
__device__ __forceinline__ uint32_t smem_u32(const void* p){
    uint32_t a;
    asm("{ .reg .u64 t; cvta.to.shared.u64 t, %1; cvt.u32.u64 %0, t; }" : "=r"(a) : "l"(p));
    return a;
}
__device__ __forceinline__ void cpa(uint32_t dst, const void* src){
    asm volatile("cp.async.ca.shared.global [%0], [%1], 16;" :: "r"(dst), "l"(src) : "memory");
}
__device__ __forceinline__ void cp_commit(){ asm volatile("cp.async.commit_group;" ::: "memory"); }
template<int NN> __device__ __forceinline__ void cp_wait(){ asm volatile("cp.async.wait_group %0;" :: "n"(NN) : "memory"); }

__device__ __forceinline__ void ldsm4(uint32_t& r0, uint32_t& r1, uint32_t& r2, uint32_t& r3, uint32_t addr){
    asm volatile("ldmatrix.sync.aligned.m8n8.x4.shared.b16 {%0,%1,%2,%3}, [%4];"
        : "=r"(r0), "=r"(r1), "=r"(r2), "=r"(r3) : "r"(addr));
}
__device__ __forceinline__ void mma16816(float* c, const uint32_t* a, const uint32_t* b){
    asm volatile(
        "mma.sync.aligned.m16n8k16.row.col.f32.f16.f16.f32 "
        "{%0,%1,%2,%3}, {%4,%5,%6,%7}, {%8,%9}, {%0,%1,%2,%3};"
        : "+f"(c[0]), "+f"(c[1]), "+f"(c[2]), "+f"(c[3])
        : "r"(a[0]), "r"(a[1]), "r"(a[2]), "r"(a[3]), "r"(b[0]), "r"(b[1]));
}

__device__ __forceinline__ int cellc(float v){
    int c = (int)floorf((v + 4.0f) * 4.0f);
    return min(max(c, 0), GC-1);
}

// exact top-3 with lexicographic (d, idx) ordering (matches top_k tie-break)
struct Top3 { float d0, d1, d2; int i0, i1, i2; };

__device__ __forceinline__ void t3_insert(Top3& t, float d, int pi){
    if (d < t.d2 || (d == t.d2 && pi < t.i2)){
        if (d < t.d1 || (d == t.d1 && pi < t.i1)){
            t.d2 = t.d1; t.i2 = t.i1;
            if (d < t.d0 || (d == t.d0 && pi < t.i0)){ t.d1 = t.d0; t.i1 = t.i0; t.d0 = d; t.i0 = pi; }
            else { t.d1 = d; t.i1 = pi; }
        } else { t.d2 = d; t.i2 = pi; }
    }
}

__device__ __forceinline__ void write_result(int q, const Top3& t){
    float e0 = fmaxf(t.d0, 1e-10f);
    float e1 = fmaxf(t.d1, 1e-10f);
    float e2 = fmaxf(t.d2, 1e-10f);
    float w0 = 1.f/e0, w1 = 1.f/e1, w2 = 1.f/e2;
    float inv = 1.f/(w0 + w1 + w2);
    g_wgt[q*3+0] = w0*inv; g_wgt[q*3+1] = w1*inv; g_wgt[q*3+2] = w2*inv;
    g_idx[q*3+0] = t.i0;   g_idx[q*3+1] = t.i1;   g_idx[q*3+2] = t.i2;
}

// ---------------- prep: pack xyz2 (+norm), zero counts, BN scale/shift ----------------
__global__ void prep_kernel(const float* __restrict__ xyz2,
                            const float* __restrict__ G0, const float* __restrict__ B0,
                            const float* __restrict__ M0, const float* __restrict__ V0,
                            const float* __restrict__ G1, const float* __restrict__ B1,
                            const float* __restrict__ M1, const float* __restrict__ V1)
{
    int i = blockIdx.x*256 + threadIdx.x;        // grid 512 -> 131072 threads
    if (i < BB*NCELL) g_cnt[i] = 0;
    if (i == 0) g_fbCnt = 0;
    if (i < BB*MP){
        float x = xyz2[i*3+0], y = xyz2[i*3+1], z = xyz2[i*3+2];
        g_xyz2p[i] = make_float4(x, y, z, x*x + y*y + z*z);
    }
    if (blockIdx.x == 0){
        int t = threadIdx.x;
        if (t < D0){ float s = G0[t]*rsqrtf(V0[t]+1e-3f); g_sc0[t]=s; g_sh0[t]=B0[t]-M0[t]*s; }
        if (t < D1){ float s = G1[t]*rsqrtf(V1[t]+1e-3f); g_sc1[t]=s; g_sh1[t]=B1[t]-M1[t]*s; }
    }
}

// ---------------- bin: cell id + slot per point ----------------
__global__ void __launch_bounds__(256) bin_kernel(const float* __restrict__ xyz2)
{
    int p = blockIdx.x*256 + threadIdx.x;        // grid 64 -> 16384
    float x = xyz2[p*3+0], y = xyz2[p*3+1], z = xyz2[p*3+2];
    int b = p >> 12;
    int cell = (cellc(z) << 10) | (cellc(y) << 5) | cellc(x);
    g_pcell[p] = cell;
    g_pslot[p] = atomicAdd(&g_cnt[(b << 15) + cell], 1);
}

// ---------------- scan (per batch, 1 block) + scatter ----------------
__global__ void __launch_bounds__(1024) scan_scatter_kernel()
{
    __shared__ int part[1024];
    const int b = blockIdx.x, t = threadIdx.x;
    const int* cnt = g_cnt + (b << 15);
    int2* sc = g_cellSC + (b << 15);

    int loc[32];
    int s = 0;
    const int base = t*32;
    #pragma unroll
    for (int k = 0; k < 32; ++k){ loc[k] = s; s += cnt[base+k]; }
    part[t] = s;
    __syncthreads();
    const int mysum = s;
    for (int off = 1; off < 1024; off <<= 1){
        int v = (t >= off) ? part[t-off] : 0;
        __syncthreads();
        part[t] += v;
        __syncthreads();
    }
    const int excl = part[t] - mysum;
    #pragma unroll
    for (int k = 0; k < 32; ++k)
        sc[base+k] = make_int2(excl + loc[k], cnt[base+k]);
    __syncthreads();

    for (int i = t; i < MP; i += 1024){
        int p = (b << 12) + i;
        int dst = sc[g_pcell[p]].x + g_pslot[p];
        g_sortP[(b << 12) + dst] = g_xyz2p[p];
        g_sortI[(b << 12) + dst] = i;
    }
}

// ---------------- search phase 1: shell-only enumeration, r <= RMAX ----------------
__device__ __forceinline__ void visit_cell(const float4* __restrict__ SP, const int* __restrict__ SI,
                                           const int2* __restrict__ SC, int cellid,
                                           float ax, float ay, float az, float n1, Top3& t)
{
    int2 sc = SC[cellid];
    const int e = sc.x + sc.y;
    for (int j = sc.x; j < e; ++j){
        float4 p = SP[j];
        float d = fmaf(az, p.z, fmaf(ay, p.y, fmaf(ax, p.x, p.w))) + n1;
        t3_insert(t, d, SI[j]);
    }
}

__global__ void __launch_bounds__(128) search1_kernel(const float* __restrict__ xyz1)
{
    const int q = blockIdx.x*128 + threadIdx.x;  // grid 512
    const int b = q >> 14;
    const float x = xyz1[q*3+0], y = xyz1[q*3+1], z = xyz1[q*3+2];
    const float n1 = x*x + y*y + z*z;
    const float ax = -2.f*x, ay = -2.f*y, az = -2.f*z;
    const int cx = cellc(x), cy = cellc(y), cz = cellc(z);

    const float4* SP = g_sortP + (b << 12);
    const int*    SI = g_sortI + (b << 12);
    const int2*   SC = g_cellSC + (b << 15);

    Top3 t = {3.0e37f, 3.0e37f, 3.0e37f, 0x7FFFFFFF, 0x7FFFFFFF, 0x7FFFFFFF};
    bool done = false;

    for (int r = 0; r <= RMAX; ++r){
        if (r == 0){
            visit_cell(SP, SI, SC, (cz << 10) | (cy << 5) | cx, ax, ay, az, n1, t);
        } else {
            const int zl = cz-r, zh = cz+r, yl = cy-r, yh = cy+r, xl = cx-r, xh = cx+r;
            const int yl0 = max(yl, 0), yh0 = min(yh, GC-1);
            const int xl0 = max(xl, 0), xh0 = min(xh, GC-1);
            const int zl1 = max(zl+1, 0), zh1 = min(zh-1, GC-1);
            const int yl1 = max(yl+1, 0), yh1 = min(yh-1, GC-1);
            // z faces (full xy extent)
            if (zl >= 0)
                for (int iy = yl0; iy <= yh0; ++iy)
                    for (int ix = xl0; ix <= xh0; ++ix)
                        visit_cell(SP, SI, SC, (zl << 10) | (iy << 5) | ix, ax, ay, az, n1, t);
            if (zh <= GC-1)
                for (int iy = yl0; iy <= yh0; ++iy)
                    for (int ix = xl0; ix <= xh0; ++ix)
                        visit_cell(SP, SI, SC, (zh << 10) | (iy << 5) | ix, ax, ay, az, n1, t);
            // y faces (interior z, full x)
            if (yl >= 0)
                for (int iz = zl1; iz <= zh1; ++iz)
                    for (int ix = xl0; ix <= xh0; ++ix)
                        visit_cell(SP, SI, SC, (iz << 10) | (yl << 5) | ix, ax, ay, az, n1, t);
            if (yh <= GC-1)
                for (int iz = zl1; iz <= zh1; ++iz)
                    for (int ix = xl0; ix <= xh0; ++ix)
                        visit_cell(SP, SI, SC, (iz << 10) | (yh << 5) | ix, ax, ay, az, n1, t);
            // x faces (interior z, interior y)
            if (xl >= 0)
                for (int iz = zl1; iz <= zh1; ++iz)
                    for (int iy = yl1; iy <= yh1; ++iy)
                        visit_cell(SP, SI, SC, (iz << 10) | (iy << 5) | xl, ax, ay, az, n1, t);
            if (xh <= GC-1)
                for (int iz = zl1; iz <= zh1; ++iz)
                    for (int iy = yl1; iy <= yh1; ++iy)
                        visit_cell(SP, SI, SC, (iz << 10) | (iy << 5) | xh, ax, ay, az, n1, t);
        }
        // exact stopping rule: min distance to any unvisited cell
        float f = 3.0e37f;
        if (cx-r > 0)    f = fminf(f, x - (-4.f + 0.25f*(float)(cx-r)));
        if (cx+r < GC-1) f = fminf(f, (-4.f + 0.25f*(float)(cx+r+1)) - x);
        if (cy-r > 0)    f = fminf(f, y - (-4.f + 0.25f*(float)(cy-r)));
        if (cy+r < GC-1) f = fminf(f, (-4.f + 0.25f*(float)(cy+r+1)) - y);
        if (cz-r > 0)    f = fminf(f, z - (-4.f + 0.25f*(float)(cz-r)));
        if (cz+r < GC-1) f = fminf(f, (-4.f + 0.25f*(float)(cz+r+1)) - z);
        if (t.d2 <= f*f*0.9998f){ done = true; break; }
    }

    if (done){
        write_result(q, t);
    } else {
        int s = atomicAdd(&g_fbCnt, 1);
        g_fbList[s] = q;
    }
}

// ---------------- fallback: one warp per unresolved query, exact full scan ----------------
__device__ __forceinline__ void merge3(Top3& a, float b0, int j0, float b1, int j1, float b2, int j2){
    float A[3] = {a.d0, a.d1, a.d2}; int AI[3] = {a.i0, a.i1, a.i2};
    float Bv[3] = {b0, b1, b2};      int BI[3] = {j0, j1, j2};
    float R[3]; int RI[3];
    int ia = 0, ib = 0;
    #pragma unroll
    for (int k = 0; k < 3; ++k){
        float av = A[ia], bv = Bv[ib];
        int aidx = AI[ia], bidx = BI[ib];
        bool ta = (av < bv) || (av == bv && aidx <= bidx);
        R[k]  = ta ? av : bv;
        RI[k] = ta ? aidx : bidx;
        ia += ta ? 1 : 0; ib += ta ? 0 : 1;
    }
    a.d0 = R[0]; a.d1 = R[1]; a.d2 = R[2];
    a.i0 = RI[0]; a.i1 = RI[1]; a.i2 = RI[2];
}

__global__ void __launch_bounds__(256) nnfb_kernel(const float* __restrict__ xyz1)
{
    const int gt = blockIdx.x*256 + threadIdx.x;
    const int w = gt >> 5, lane = gt & 31;
    const int nw = gridDim.x * 8;
    const int cnt = g_fbCnt;

    for (int u = w; u < cnt; u += nw){
        const int q = g_fbList[u];
        const int b = q >> 14;
        const float x = xyz1[q*3+0], y = xyz1[q*3+1], z = xyz1[q*3+2];
        const float n1 = x*x + y*y + z*z;
        const float ax = -2.f*x, ay = -2.f*y, az = -2.f*z;
        const float4* P = g_xyz2p + b*MP;

        Top3 t = {3.0e37f, 3.0e37f, 3.0e37f, 0x7FFFFFFF, 0x7FFFFFFF, 0x7FFFFFFF};
        for (int k = lane; k < MP; k += 32){
            float4 p = P[k];
            float d = fmaf(az, p.z, fmaf(ay, p.y, fmaf(ax, p.x, p.w))) + n1;
            t3_insert(t, d, k);
        }
        #pragma unroll
        for (int off = 16; off > 0; off >>= 1){
            float e0 = __shfl_xor_sync(0xFFFFFFFF, t.d0, off);
            float e1 = __shfl_xor_sync(0xFFFFFFFF, t.d1, off);
            float e2 = __shfl_xor_sync(0xFFFFFFFF, t.d2, off);
            int   j0 = __shfl_xor_sync(0xFFFFFFFF, t.i0, off);
            int   j1 = __shfl_xor_sync(0xFFFFFFFF, t.i1, off);
            int   j2 = __shfl_xor_sync(0xFFFFFFFF, t.i2, off);
            merge3(t, e0, j0, e1, j1, e2, j2);
        }
        if (lane == 0) write_result(q, t);
    }
}

// ---------------- fp32 -> fp16 vector convert ----------------
__global__ void __launch_bounds__(256) f2h_kernel(const float4* __restrict__ in, __half2* __restrict__ out){
    int i = blockIdx.x*256 + threadIdx.x;
    float4 v = in[i];
    out[2*i+0] = __floats2half2_rn(v.x, v.y);
    out[2*i+1] = __floats2half2_rn(v.z, v.w);
}

// ---------------- weight transpose + fp16 (K-major for B operand) ----------------
__global__ void __launch_bounds__(256) wtrans_kernel(const float* __restrict__ w0, const float* __restrict__ w1){
    int t = blockIdx.x*256 + threadIdx.x;            // 0..131071
    if (t < 65536){
        int n = t >> 8, k = t & 255;
        g_W0a[n*256 + k] = __float2half_rn(w0[k*256 + n]);
    } else if (t < 98304){
        int u = t - 65536; int n = u >> 7, k = u & 127;
        g_W0b[n*128 + k] = __float2half_rn(w0[(256 + k)*256 + n]);
    } else {
        int u = t - 98304; int n = u >> 8, k = u & 255;
        g_W1h[n*256 + k] = __float2half_rn(w1[k*128 + n]);
    }
}

// ---------------- weighted gather of P2W rows -> fp16 first-layer partial ----------------
__global__ void __launch_bounds__(256) gather_kernel()
{
    int t = blockIdx.x*256 + threadIdx.x;
    int q = t >> 6;
    int c = t & 63;
    int b = q >> 14;
    float w0 = g_wgt[q*3+0], w1 = g_wgt[q*3+1], w2 = g_wgt[q*3+2];
    const float4* P = (const float4*)g_P2W;
    int base = b * (MP * (D0/4));
    float4 p0 = P[base + g_idx[q*3+0]*(D0/4) + c];
    float4 p1 = P[base + g_idx[q*3+1]*(D0/4) + c];
    float4 p2 = P[base + g_idx[q*3+2]*(D0/4) + c];
    float rx = w0*p0.x + w1*p1.x + w2*p2.x;
    float ry = w0*p0.y + w1*p1.y + w2*p2.y;
    float rz = w0*p0.z + w1*p1.z + w2*p2.z;
    float rw = w0*p0.w + w1*p1.w + w2*p2.w;
    __half2* o = (__half2*)g_G1h;
    o[((size_t)q*D0 >> 1) + c*2 + 0] = __floats2half2_rn(rx, ry);
    o[((size_t)q*D0 >> 1) + c*2 + 1] = __floats2half2_rn(rz, rw);
}

// ---------------- fp16 tensor-core GEMM: out = epi(A[M,K]h @ Bt[Nc,K]h^T (+G1h)) ------
template<bool GATHER, bool BN, bool OUT_HALF>
__global__ void __launch_bounds__(256) gemm_h(
    const __half* __restrict__ A, const __half* __restrict__ Bt,
    const float* __restrict__ scale, const float* __restrict__ shift,
    void* __restrict__ outv, int K, int NcOut)
{
    __shared__ __half As[2][128*40];
    __shared__ __half Bs[2][128*40];

    const int tid  = threadIdx.x;
    const int lane = tid & 31, warp = tid >> 5;
    const int wm = warp & 3, wn = warp >> 2;
    const int mBase = blockIdx.x * 128;
    const int nBase = blockIdx.y * 128;

    float acc[2][8][4];
    #pragma unroll
    for (int mt = 0; mt < 2; ++mt)
        #pragma unroll
        for (int nt = 0; nt < 8; ++nt)
            #pragma unroll
            for (int c = 0; c < 4; ++c) acc[mt][nt][c] = 0.f;

    const uint32_t sA_[2] = { smem_u32(As[0]), smem_u32(As[1]) };
    const uint32_t sB_[2] = { smem_u32(Bs[0]), smem_u32(Bs[1]) };

    const int g  = lane >> 3, lr = lane & 7;
    const uint32_t offA = (uint32_t)((wm*32 + (g&1)*8 + lr)*40 + (g>>1)*8);
    const uint32_t offB = (uint32_t)((wn*64 + (g>>1)*8 + lr)*40 + (g&1)*8);

    const int lrow = tid >> 1;
    const int lseg2 = (tid & 1) * 2;
    const __half* Ag = A + (size_t)(mBase + lrow)*K + lseg2*8;
    const __half* Bg = Bt + (size_t)(nBase + lrow)*K + lseg2*8;
    const uint32_t dA = (uint32_t)(lrow*40 + lseg2*8)*2;
    const uint32_t dB = dA;

    auto load_tile = [&](int kc, int buf){
        const __half* a = Ag + kc*32;
        const __half* b = Bg + kc*32;
        cpa(sA_[buf] + dA,      a);
        cpa(sA_[buf] + dA + 16, a + 8);
        cpa(sB_[buf] + dB,      b);
        cpa(sB_[buf] + dB + 16, b + 8);
        cp_commit();
    };

    const int KC = K >> 5;
    load_tile(0, 0);
    for (int kc = 0; kc < KC; ++kc){
        const int buf = kc & 1;
        if (kc + 1 < KC){ load_tile(kc+1, buf^1); cp_wait<1>(); }
        else            { cp_wait<0>(); }
        __syncthreads();

        const uint32_t sA = sA_[buf], sB = sB_[buf];
        #pragma unroll
        for (int ks = 0; ks < 2; ++ks){
            uint32_t af[2][4];
            uint32_t bf[8][2];
            #pragma unroll
            for (int mt = 0; mt < 2; ++mt)
                ldsm4(af[mt][0], af[mt][1], af[mt][2], af[mt][3],
                      sA + (offA + mt*16*40 + ks*16)*2);
            #pragma unroll
            for (int ntp = 0; ntp < 4; ++ntp)
                ldsm4(bf[2*ntp][0], bf[2*ntp][1], bf[2*ntp+1][0], bf[2*ntp+1][1],
                      sB + (offB + ntp*16*40 + ks*16)*2);
            #pragma unroll
            for (int mt = 0; mt < 2; ++mt)
                #pragma unroll
                for (int nt = 0; nt < 8; ++nt)
                    mma16816(acc[mt][nt], af[mt], bf[nt]);
        }
        __syncthreads();
    }

    #pragma unroll
    for (int mt = 0; mt < 2; ++mt){
        #pragma unroll
        for (int h = 0; h < 2; ++h){
            const int r = mBase + wm*32 + mt*16 + (lane >> 2) + h*8;
            const __half* g1row = GATHER ? (g_G1h + (size_t)r*D0) : nullptr;
            #pragma unroll
            for (int nt = 0; nt < 8; ++nt){
                const int c = nBase + wn*64 + nt*8 + (lane & 3)*2;
                float v0 = acc[mt][nt][h*2+0];
                float v1 = acc[mt][nt][h*2+1];
                if (GATHER){
                    float2 gg = __half22float2(*(const __half2*)(g1row + c));
                    v0 += gg.x; v1 += gg.y;
                }
                if (BN){
                    float2 sc = *(const float2*)(scale + c);
                    float2 sh = *(const float2*)(shift + c);
                    v0 = fmaxf(fmaf(v0, sc.x, sh.x), 0.f);
                    v1 = fmaxf(fmaf(v1, sc.y, sh.y), 0.f);
                }
                if (OUT_HALF){
                    __half2* o = (__half2*)outv;
                    o[((size_t)r*NcOut + c) >> 1] = __floats2half2_rn(v0, v1);
                } else {
                    float2* o = (float2*)outv;
                    o[((size_t)r*NcOut + c) >> 1] = make_float2(v0, v1);
                }
            }
        }
    }
}

// ---------------- launch ----------------
extern "C" void kernel_launch(void* const* d_in, const int* in_sizes, int n_in,
                              void* d_out, int out_size)
{
    const float* xyz1    = (const float*)d_in[0];
    const float* xyz2    = (const float*)d_in[1];
    const float* points1 = (const float*)d_in[2];
    const float* points2 = (const float*)d_in[3];
    const float* w0 = (const float*)d_in[4];
    const float* g0 = (const float*)d_in[5];
    const float* b0 = (const float*)d_in[6];
    const float* m0 = (const float*)d_in[7];
    const float* v0 = (const float*)d_in[8];
    const float* w1 = (const float*)d_in[9];
    const float* g1 = (const float*)d_in[10];
    const float* b1 = (const float*)d_in[11];
    const float* m1 = (const float*)d_in[12];
    const float* v1 = (const float*)d_in[13];
    float* out = (float*)d_out;

    void *pA1h=nullptr, *pA2h=nullptr, *pW0a=nullptr, *pW0b=nullptr, *pW1h=nullptr,
         *pP2W=nullptr, *pHh=nullptr, *pSc0=nullptr, *pSh0=nullptr, *pSc1=nullptr, *pSh1=nullptr;
    cudaGetSymbolAddress(&pA1h, g_A1h);
    cudaGetSymbolAddress(&pA2h, g_A2h);
    cudaGetSymbolAddress(&pW0a, g_W0a);
    cudaGetSymbolAddress(&pW0b, g_W0b);
    cudaGetSymbolAddress(&pW1h, g_W1h);
    cudaGetSymbolAddress(&pP2W, g_P2W);
    cudaGetSymbolAddress(&pHh,  g_Hh);
    cudaGetSymbolAddress(&pSc0, g_sc0);
    cudaGetSymbolAddress(&pSh0, g_sh0);
    cudaGetSymbolAddress(&pSc1, g_sc1);
    cudaGetSymbolAddress(&pSh1, g_sh1);

    // 1) pack xyz2 + zero counts + BN constants
    prep_kernel<<<512, 256>>>(xyz2, g0, b0, m0, v0, g1, b1, m1, v1);

    // 2) bin points into 32^3 grid
    bin_kernel<<<64, 256>>>(xyz2);

    // 3) per-batch prefix scan + scatter into cell-sorted order
    scan_scatter_kernel<<<4, 1024>>>();

    // 4) phase-1 shell search, r<=4 (profiled slot)
    search1_kernel<<<512, 128>>>(xyz1);

    // 5) fallback: exact full scan for unresolved queries
    nnfb_kernel<<<256, 256>>>(xyz1);

    // 6-7) fp16 conversions of activations
    f2h_kernel<<<NTOT*C1V/4/256, 256>>>((const float4*)points1, (__half2*)pA1h);
    f2h_kernel<<<BB*MP*C2V/4/256, 256>>>((const float4*)points2, (__half2*)pA2h);

    // 8) weight transpose + fp16
    wtrans_kernel<<<512, 256>>>(w0, w1);

    // 9) P2W = points2 @ w0[0:256,:]   (M=16384, K=256, N=256) -> fp32
    gemm_h<false,false,false><<<dim3(128, 2), 256>>>(
        (const __half*)pA2h, (const __half*)pW0a, nullptr, nullptr, pP2W, 256, 256);

    // 10) G1h = weighted gather of P2W rows -> fp16
    gather_kernel<<<16384, 256>>>();

    // 11) H = relu(bn0(points1 @ w0[256:384,:] + G1h)) -> fp16
    gemm_h<true,true,true><<<dim3(512, 2), 256>>>(
        (const __half*)pA1h, (const __half*)pW0b,
        (const float*)pSc0, (const float*)pSh0, pHh, 128, 256);

    // 12) out = relu(bn1(H @ w1)) -> fp32
    gemm_h<false,true,false><<<dim3(512, 1), 256>>>(
        (const __half*)pHh, (const __half*)pW1h,
        (const float*)pSc1, (const float*)pSh1, out, 256, 128);
}

// round 13
// speedup vs baseline: 4.1227x; 1.4286x over previous
#include <cuda_runtime.h>
#include <cuda_fp16.h>
#include <cstdint>
#include <cstddef>

#define BB 4
#define NQ 16384
#define MP 4096
#define C1V 128
#define C2V 256
#define D0 256
#define D1 128
#define NTOT (BB*NQ)   // 65536
#define GC 16          // cells per axis (cell = 0.5, span [-4,4))
#define NCELL (GC*GC*GC)

// ---------------- scratch (device globals; no allocation allowed) ----------------
__device__ float4 g_xyz2p[BB*MP];                  // packed xyz2 + norm
__device__ float  g_sc0[D0], g_sh0[D0], g_sc1[D1], g_sh1[D1];
__device__ float  g_wgt[NTOT*3];
__device__ int    g_idx[NTOT*3];
__device__ int    g_cnt[BB*NCELL];                 // per-cell point counts
__device__ int2   g_cellSC[BB*NCELL];              // per-cell (start, count)
__device__ int    g_pcell[BB*MP], g_pslot[BB*MP];
__device__ float4 g_sortP[BB*MP];                  // cell-sorted points (+norm)
__device__ int    g_sortI[BB*MP];                  // original in-batch index
__device__ int    g_fbCnt;                         // fallback query count
__device__ int    g_fbList[NTOT];                  // fallback query ids
__device__ __half g_A1h[(size_t)NTOT*C1V];
__device__ __half g_A2h[BB*MP*C2V];
__device__ __half g_W0a[256*256];
__device__ __half g_W0b[256*128];
__device__ __half g_W1h[128*256];
__device__ float  g_P2W[BB*MP*D0];
__device__ __half g_G1h[(size_t)NTOT*D0];
__device__ __half g_Hh[(size_t)NTOT*D0];

// ---------------- PTX helpers ----------------
__device__ __forceinline__ uint32_t smem_u32(const void* p){
    uint32_t a;
    asm("{ .reg .u64 t; cvta.to.shared.u64 t, %1; cvt.u32.u64 %0, t; }" : "=r"(a) : "l"(p));
    return a;
}
__device__ __forceinline__ void cpa(uint32_t dst, const void* src){
    asm volatile("cp.async.ca.shared.global [%0], [%1], 16;" :: "r"(dst), "l"(src) : "memory");
}
__device__ __forceinline__ void cp_commit(){ asm volatile("cp.async.commit_group;" ::: "memory"); }
template<int NN> __device__ __forceinline__ void cp_wait(){ asm volatile("cp.async.wait_group %0;" :: "n"(NN) : "memory"); }

__device__ __forceinline__ void ldsm4(uint32_t& r0, uint32_t& r1, uint32_t& r2, uint32_t& r3, uint32_t addr){
    asm volatile("ldmatrix.sync.aligned.m8n8.x4.shared.b16 {%0,%1,%2,%3}, [%4];"
        : "=r"(r0), "=r"(r1), "=r"(r2), "=r"(r3) : "r"(addr));
}
__device__ __forceinline__ void mma16816(float* c, const uint32_t* a, const uint32_t* b){
    asm volatile(
        "mma.sync.aligned.m16n8k16.row.col.f32.f16.f16.f32 "
        "{%0,%1,%2,%3}, {%4,%5,%6,%7}, {%8,%9}, {%0,%1,%2,%3};"
        : "+f"(c[0]), "+f"(c[1]), "+f"(c[2]), "+f"(c[3])
        : "r"(a[0]), "r"(a[1]), "r"(a[2]), "r"(a[3]), "r"(b[0]), "r"(b[1]));
}

__device__ __forceinline__ int cellc(float v){
    int c = (int)floorf((v + 4.0f) * 2.0f);
    return min(max(c, 0), GC-1);
}

// exact top-3 with lexicographic (d, idx) ordering (matches top_k tie-break)
struct Top3 { float d0, d1, d2; int i0, i1, i2; };

__device__ __forceinline__ void t3_insert(Top3& t, float d, int pi){
    if (d < t.d2 || (d == t.d2 && pi < t.i2)){
        if (d < t.d1 || (d == t.d1 && pi < t.i1)){
            t.d2 = t.d1; t.i2 = t.i1;
            if (d < t.d0 || (d == t.d0 && pi < t.i0)){ t.d1 = t.d0; t.i1 = t.i0; t.d0 = d; t.i0 = pi; }
            else { t.d1 = d; t.i1 = pi; }
        } else { t.d2 = d; t.i2 = pi; }
    }
}

__device__ __forceinline__ void merge3(Top3& a, float b0, int j0, float b1, int j1, float b2, int j2){
    float A[3] = {a.d0, a.d1, a.d2}; int AI[3] = {a.i0, a.i1, a.i2};
    float Bv[3] = {b0, b1, b2};      int BI[3] = {j0, j1, j2};
    float R[3]; int RI[3];
    int ia = 0, ib = 0;
    #pragma unroll
    for (int k = 0; k < 3; ++k){
        float av = A[ia], bv = Bv[ib];
        int aidx = AI[ia], bidx = BI[ib];
        bool ta = (av < bv) || (av == bv && aidx <= bidx);
        R[k]  = ta ? av : bv;
        RI[k] = ta ? aidx : bidx;
        ia += ta ? 1 : 0; ib += ta ? 0 : 1;
    }
    a.d0 = R[0]; a.d1 = R[1]; a.d2 = R[2];
    a.i0 = RI[0]; a.i1 = RI[1]; a.i2 = RI[2];
}

__device__ __forceinline__ void warp_reduce_top3(Top3& t){
    #pragma unroll
    for (int off = 16; off > 0; off >>= 1){
        float e0 = __shfl_xor_sync(0xFFFFFFFF, t.d0, off);
        float e1 = __shfl_xor_sync(0xFFFFFFFF, t.d1, off);
        float e2 = __shfl_xor_sync(0xFFFFFFFF, t.d2, off);
        int   j0 = __shfl_xor_sync(0xFFFFFFFF, t.i0, off);
        int   j1 = __shfl_xor_sync(0xFFFFFFFF, t.i1, off);
        int   j2 = __shfl_xor_sync(0xFFFFFFFF, t.i2, off);
        merge3(t, e0, j0, e1, j1, e2, j2);
    }
}

__device__ __forceinline__ void write_result(int q, const Top3& t){
    float e0 = fmaxf(t.d0, 1e-10f);
    float e1 = fmaxf(t.d1, 1e-10f);
    float e2 = fmaxf(t.d2, 1e-10f);
    float w0 = 1.f/e0, w1 = 1.f/e1, w2 = 1.f/e2;
    float inv = 1.f/(w0 + w1 + w2);
    g_wgt[q*3+0] = w0*inv; g_wgt[q*3+1] = w1*inv; g_wgt[q*3+2] = w2*inv;
    g_idx[q*3+0] = t.i0;   g_idx[q*3+1] = t.i1;   g_idx[q*3+2] = t.i2;
}

// ---------------- prep: pack xyz2 (+norm), zero counts, BN scale/shift ----------------
__global__ void prep_kernel(const float* __restrict__ xyz2,
                            const float* __restrict__ G0, const float* __restrict__ B0,
                            const float* __restrict__ M0, const float* __restrict__ V0,
                            const float* __restrict__ G1, const float* __restrict__ B1,
                            const float* __restrict__ M1, const float* __restrict__ V1)
{
    int i = blockIdx.x*256 + threadIdx.x;        // grid 64 -> 16384 threads
    if (i < BB*NCELL) g_cnt[i] = 0;
    if (i == 0) g_fbCnt = 0;
    if (i < BB*MP){
        float x = xyz2[i*3+0], y = xyz2[i*3+1], z = xyz2[i*3+2];
        g_xyz2p[i] = make_float4(x, y, z, x*x + y*y + z*z);
    }
    if (blockIdx.x == 0){
        int t = threadIdx.x;
        if (t < D0){ float s = G0[t]*rsqrtf(V0[t]+1e-3f); g_sc0[t]=s; g_sh0[t]=B0[t]-M0[t]*s; }
        if (t < D1){ float s = G1[t]*rsqrtf(V1[t]+1e-3f); g_sc1[t]=s; g_sh1[t]=B1[t]-M1[t]*s; }
    }
}

// ---------------- bin: cell id + slot per point ----------------
__global__ void __launch_bounds__(256) bin_kernel(const float* __restrict__ xyz2)
{
    int p = blockIdx.x*256 + threadIdx.x;        // grid 64 -> 16384
    float x = xyz2[p*3+0], y = xyz2[p*3+1], z = xyz2[p*3+2];
    int b = p >> 12;
    int cell = (cellc(z) << 8) | (cellc(y) << 4) | cellc(x);
    g_pcell[p] = cell;
    g_pslot[p] = atomicAdd(&g_cnt[b*NCELL + cell], 1);
}

// ---------------- scan (per batch, 1 block of 1024) + scatter ----------------
__global__ void __launch_bounds__(1024) scan_scatter_kernel()
{
    __shared__ int part[1024];
    const int b = blockIdx.x, t = threadIdx.x;
    const int* cnt = g_cnt + b*NCELL;
    int2* sc = g_cellSC + b*NCELL;

    int loc[4];
    int s = 0;
    const int base = t*4;
    #pragma unroll
    for (int k = 0; k < 4; ++k){ loc[k] = s; s += cnt[base+k]; }
    part[t] = s;
    __syncthreads();
    const int mysum = s;
    for (int off = 1; off < 1024; off <<= 1){
        int v = (t >= off) ? part[t-off] : 0;
        __syncthreads();
        part[t] += v;
        __syncthreads();
    }
    const int excl = part[t] - mysum;
    #pragma unroll
    for (int k = 0; k < 4; ++k)
        sc[base+k] = make_int2(excl + loc[k], cnt[base+k]);
    __syncthreads();

    for (int i = t; i < MP; i += 1024){
        int p = (b << 12) + i;
        int dst = sc[g_pcell[p]].x + g_pslot[p];
        g_sortP[(b << 12) + dst] = g_xyz2p[p];
        g_sortI[(b << 12) + dst] = i;
    }
}

// ------- search: warp per query, 27-cell box, lanes own cells, exact stop rule -------
__global__ void __launch_bounds__(256) search_kernel(const float* __restrict__ xyz1)
{
    const int q = (blockIdx.x*256 + threadIdx.x) >> 5;   // warp id = query
    const int lane = threadIdx.x & 31;
    const int b = q >> 14;
    const float x = xyz1[q*3+0], y = xyz1[q*3+1], z = xyz1[q*3+2];
    const float n1 = x*x + y*y + z*z;
    const float ax = -2.f*x, ay = -2.f*y, az = -2.f*z;
    const int cx = cellc(x), cy = cellc(y), cz = cellc(z);

    const float4* SP = g_sortP + (b << 12);
    const int*    SI = g_sortI + (b << 12);
    const int2*   SC = g_cellSC + b*NCELL;

    Top3 t = {3.0e37f, 3.0e37f, 3.0e37f, 0x7FFFFFFF, 0x7FFFFFFF, 0x7FFFFFFF};

    if (lane < 27){
        const int ix = cx + (lane % 3) - 1;
        const int iy = cy + ((lane / 3) % 3) - 1;
        const int iz = cz + (lane / 9) - 1;
        if (ix >= 0 && ix < GC && iy >= 0 && iy < GC && iz >= 0 && iz < GC){
            int2 sc = SC[(iz << 8) | (iy << 4) | ix];
            const int e = sc.x + sc.y;
            for (int j = sc.x; j < e; ++j){
                float4 p = SP[j];
                float d = fmaf(az, p.z, fmaf(ay, p.y, fmaf(ax, p.x, p.w))) + n1;
                t3_insert(t, d, SI[j]);
            }
        }
    }
    warp_reduce_top3(t);

    // exact stop rule: min distance from query to any face with unvisited cells beyond
    float f = 3.0e37f;
    if (cx-1 > 0)    f = fminf(f, x - (0.5f*(float)(cx-1) - 4.f));
    if (cx+1 < GC-1) f = fminf(f, (0.5f*(float)(cx+2) - 4.f) - x);
    if (cy-1 > 0)    f = fminf(f, y - (0.5f*(float)(cy-1) - 4.f));
    if (cy+1 < GC-1) f = fminf(f, (0.5f*(float)(cy+2) - 4.f) - y);
    if (cz-1 > 0)    f = fminf(f, z - (0.5f*(float)(cz-1) - 4.f));
    if (cz+1 < GC-1) f = fminf(f, (0.5f*(float)(cz+2) - 4.f) - z);

    if (lane == 0){
        if (t.d2 <= f*f*0.9998f){
            write_result(q, t);
        } else {
            int s = atomicAdd(&g_fbCnt, 1);
            g_fbList[s] = q;
        }
    }
}

// ---------------- fallback: one warp per unresolved query, exact full scan ----------------
__global__ void __launch_bounds__(256) nnfb_kernel(const float* __restrict__ xyz1)
{
    const int gt = blockIdx.x*256 + threadIdx.x;
    const int w = gt >> 5, lane = gt & 31;
    const int nw = gridDim.x * 8;
    const int cnt = g_fbCnt;

    for (int u = w; u < cnt; u += nw){
        const int q = g_fbList[u];
        const int b = q >> 14;
        const float x = xyz1[q*3+0], y = xyz1[q*3+1], z = xyz1[q*3+2];
        const float n1 = x*x + y*y + z*z;
        const float ax = -2.f*x, ay = -2.f*y, az = -2.f*z;
        const float4* P = g_xyz2p + b*MP;

        Top3 t = {3.0e37f, 3.0e37f, 3.0e37f, 0x7FFFFFFF, 0x7FFFFFFF, 0x7FFFFFFF};
        for (int k = lane; k < MP; k += 32){
            float4 p = P[k];
            float d = fmaf(az, p.z, fmaf(ay, p.y, fmaf(ax, p.x, p.w))) + n1;
            t3_insert(t, d, k);
        }
        warp_reduce_top3(t);
        if (lane == 0) write_result(q, t);
    }
}

// ---------------- fp32 -> fp16 vector convert ----------------
__global__ void __launch_bounds__(256) f2h_kernel(const float4* __restrict__ in, __half2* __restrict__ out){
    int i = blockIdx.x*256 + threadIdx.x;
    float4 v = in[i];
    out[2*i+0] = __floats2half2_rn(v.x, v.y);
    out[2*i+1] = __floats2half2_rn(v.z, v.w);
}

// ---------------- weight transpose + fp16 (K-major for B operand) ----------------
__global__ void __launch_bounds__(256) wtrans_kernel(const float* __restrict__ w0, const float* __restrict__ w1){
    int t = blockIdx.x*256 + threadIdx.x;            // 0..131071
    if (t < 65536){
        int n = t >> 8, k = t & 255;
        g_W0a[n*256 + k] = __float2half_rn(w0[k*256 + n]);
    } else if (t < 98304){
        int u = t - 65536; int n = u >> 7, k = u & 127;
        g_W0b[n*128 + k] = __float2half_rn(w0[(256 + k)*256 + n]);
    } else {
        int u = t - 98304; int n = u >> 8, k = u & 255;
        g_W1h[n*256 + k] = __float2half_rn(w1[k*128 + n]);
    }
}

// ---------------- weighted gather of P2W rows -> fp16 first-layer partial ----------------
__global__ void __launch_bounds__(256) gather_kernel()
{
    int t = blockIdx.x*256 + threadIdx.x;
    int q = t >> 6;
    int c = t & 63;
    int b = q >> 14;
    float w0 = g_wgt[q*3+0], w1 = g_wgt[q*3+1], w2 = g_wgt[q*3+2];
    const float4* P = (const float4*)g_P2W;
    int base = b * (MP * (D0/4));
    float4 p0 = P[base + g_idx[q*3+0]*(D0/4) + c];
    float4 p1 = P[base + g_idx[q*3+1]*(D0/4) + c];
    float4 p2 = P[base + g_idx[q*3+2]*(D0/4) + c];
    float rx = w0*p0.x + w1*p1.x + w2*p2.x;
    float ry = w0*p0.y + w1*p1.y + w2*p2.y;
    float rz = w0*p0.z + w1*p1.z + w2*p2.z;
    float rw = w0*p0.w + w1*p1.w + w2*p2.w;
    __half2* o = (__half2*)g_G1h;
    o[((size_t)q*D0 >> 1) + c*2 + 0] = __floats2half2_rn(rx, ry);
    o[((size_t)q*D0 >> 1) + c*2 + 1] = __floats2half2_rn(rz, rw);
}

// ---------------- fp16 tensor-core GEMM: out = epi(A[M,K]h @ Bt[Nc,K]h^T (+G1h)) ------
template<bool GATHER, bool BN, bool OUT_HALF>
__global__ void __launch_bounds__(256) gemm_h(
    const __half* __restrict__ A, const __half* __restrict__ Bt,
    const float* __restrict__ scale, const float* __restrict__ shift,
    void* __restrict__ outv, int K, int NcOut)
{
    __shared__ __half As[2][128*40];
    __shared__ __half Bs[2][128*40];

    const int tid  = threadIdx.x;
    const int lane = tid & 31, warp = tid >> 5;
    const int wm = warp & 3, wn = warp >> 2;
    const int mBase = blockIdx.x * 128;
    const int nBase = blockIdx.y * 128;

    float acc[2][8][4];
    #pragma unroll
    for (int mt = 0; mt < 2; ++mt)
        #pragma unroll
        for (int nt = 0; nt < 8; ++nt)
            #pragma unroll
            for (int c = 0; c < 4; ++c) acc[mt][nt][c] = 0.f;

    const uint32_t sA_[2] = { smem_u32(As[0]), smem_u32(As[1]) };
    const uint32_t sB_[2] = { smem_u32(Bs[0]), smem_u32(Bs[1]) };

    const int g  = lane >> 3, lr = lane & 7;
    const uint32_t offA = (uint32_t)((wm*32 + (g&1)*8 + lr)*40 + (g>>1)*8);
    const uint32_t offB = (uint32_t)((wn*64 + (g>>1)*8 + lr)*40 + (g&1)*8);

    const int lrow = tid >> 1;
    const int lseg2 = (tid & 1) * 2;
    const __half* Ag = A + (size_t)(mBase + lrow)*K + lseg2*8;
    const __half* Bg = Bt + (size_t)(nBase + lrow)*K + lseg2*8;
    const uint32_t dA = (uint32_t)(lrow*40 + lseg2*8)*2;
    const uint32_t dB = dA;

    auto load_tile = [&](int kc, int buf){
        const __half* a = Ag + kc*32;
        const __half* b = Bg + kc*32;
        cpa(sA_[buf] + dA,      a);
        cpa(sA_[buf] + dA + 16, a + 8);
        cpa(sB_[buf] + dB,      b);
        cpa(sB_[buf] + dB + 16, b + 8);
        cp_commit();
    };

    const int KC = K >> 5;
    load_tile(0, 0);
    for (int kc = 0; kc < KC; ++kc){
        const int buf = kc & 1;
        if (kc + 1 < KC){ load_tile(kc+1, buf^1); cp_wait<1>(); }
        else            { cp_wait<0>(); }
        __syncthreads();

        const uint32_t sA = sA_[buf], sB = sB_[buf];
        #pragma unroll
        for (int ks = 0; ks < 2; ++ks){
            uint32_t af[2][4];
            uint32_t bf[8][2];
            #pragma unroll
            for (int mt = 0; mt < 2; ++mt)
                ldsm4(af[mt][0], af[mt][1], af[mt][2], af[mt][3],
                      sA + (offA + mt*16*40 + ks*16)*2);
            #pragma unroll
            for (int ntp = 0; ntp < 4; ++ntp)
                ldsm4(bf[2*ntp][0], bf[2*ntp][1], bf[2*ntp+1][0], bf[2*ntp+1][1],
                      sB + (offB + ntp*16*40 + ks*16)*2);
            #pragma unroll
            for (int mt = 0; mt < 2; ++mt)
                #pragma unroll
                for (int nt = 0; nt < 8; ++nt)
                    mma16816(acc[mt][nt], af[mt], bf[nt]);
        }
        __syncthreads();
    }

    #pragma unroll
    for (int mt = 0; mt < 2; ++mt){
        #pragma unroll
        for (int h = 0; h < 2; ++h){
            const int r = mBase + wm*32 + mt*16 + (lane >> 2) + h*8;
            const __half* g1row = GATHER ? (g_G1h + (size_t)r*D0) : nullptr;
            #pragma unroll
            for (int nt = 0; nt < 8; ++nt){
                const int c = nBase + wn*64 + nt*8 + (lane & 3)*2;
                float v0 = acc[mt][nt][h*2+0];
                float v1 = acc[mt][nt][h*2+1];
                if (GATHER){
                    float2 gg = __half22float2(*(const __half2*)(g1row + c));
                    v0 += gg.x; v1 += gg.y;
                }
                if (BN){
                    float2 sc = *(const float2*)(scale + c);
                    float2 sh = *(const float2*)(shift + c);
                    v0 = fmaxf(fmaf(v0, sc.x, sh.x), 0.f);
                    v1 = fmaxf(fmaf(v1, sc.y, sh.y), 0.f);
                }
                if (OUT_HALF){
                    __half2* o = (__half2*)outv;
                    o[((size_t)r*NcOut + c) >> 1] = __floats2half2_rn(v0, v1);
                } else {
                    float2* o = (float2*)outv;
                    o[((size_t)r*NcOut + c) >> 1] = make_float2(v0, v1);
                }
            }
        }
    }
}

// ---------------- launch ----------------
extern "C" void kernel_launch(void* const* d_in, const int* in_sizes, int n_in,
                              void* d_out, int out_size)
{
    const float* xyz1    = (const float*)d_in[0];
    const float* xyz2    = (const float*)d_in[1];
    const float* points1 = (const float*)d_in[2];
    const float* points2 = (const float*)d_in[3];
    const float* w0 = (const float*)d_in[4];
    const float* g0 = (const float*)d_in[5];
    const float* b0 = (const float*)d_in[6];
    const float* m0 = (const float*)d_in[7];
    const float* v0 = (const float*)d_in[8];
    const float* w1 = (const float*)d_in[9];
    const float* g1 = (const float*)d_in[10];
    const float* b1 = (const float*)d_in[11];
    const float* m1 = (const float*)d_in[12];
    const float* v1 = (const float*)d_in[13];
    float* out = (float*)d_out;

    void *pA1h=nullptr, *pA2h=nullptr, *pW0a=nullptr, *pW0b=nullptr, *pW1h=nullptr,
         *pP2W=nullptr, *pHh=nullptr, *pSc0=nullptr, *pSh0=nullptr, *pSc1=nullptr, *pSh1=nullptr;
    cudaGetSymbolAddress(&pA1h, g_A1h);
    cudaGetSymbolAddress(&pA2h, g_A2h);
    cudaGetSymbolAddress(&pW0a, g_W0a);
    cudaGetSymbolAddress(&pW0b, g_W0b);
    cudaGetSymbolAddress(&pW1h, g_W1h);
    cudaGetSymbolAddress(&pP2W, g_P2W);
    cudaGetSymbolAddress(&pHh,  g_Hh);
    cudaGetSymbolAddress(&pSc0, g_sc0);
    cudaGetSymbolAddress(&pSh0, g_sh0);
    cudaGetSymbolAddress(&pSc1, g_sc1);
    cudaGetSymbolAddress(&pSh1, g_sh1);

    // 1) pack xyz2 + zero counts + BN constants
    prep_kernel<<<64, 256>>>(xyz2, g0, b0, m0, v0, g1, b1, m1, v1);

    // 2) bin points into 16^3 grid
    bin_kernel<<<64, 256>>>(xyz2);

    // 3) per-batch prefix scan + scatter into cell-sorted order
    scan_scatter_kernel<<<4, 1024>>>();

    // 4) warp-per-query 27-cell box search (profiled slot)
    search_kernel<<<8192, 256>>>(xyz1);

    // 5) fallback: exact full scan for unresolved queries
    nnfb_kernel<<<256, 256>>>(xyz1);

    // 6-7) fp16 conversions of activations
    f2h_kernel<<<NTOT*C1V/4/256, 256>>>((const float4*)points1, (__half2*)pA1h);
    f2h_kernel<<<BB*MP*C2V/4/256, 256>>>((const float4*)points2, (__half2*)pA2h);

    // 8) weight transpose + fp16
    wtrans_kernel<<<512, 256>>>(w0, w1);

    // 9) P2W = points2 @ w0[0:256,:]   (M=16384, K=256, N=256) -> fp32
    gemm_h<false,false,false><<<dim3(128, 2), 256>>>(
        (const __half*)pA2h, (const __half*)pW0a, nullptr, nullptr, pP2W, 256, 256);

    // 10) G1h = weighted gather of P2W rows -> fp16
    gather_kernel<<<16384, 256>>>();

    // 11) H = relu(bn0(points1 @ w0[256:384,:] + G1h)) -> fp16
    gemm_h<true,true,true><<<dim3(512, 2), 256>>>(
        (const __half*)pA1h, (const __half*)pW0b,
        (const float*)pSc0, (const float*)pSh0, pHh, 128, 256);

    // 12) out = relu(bn1(H @ w1)) -> fp32
    gemm_h<false,true,false><<<dim3(512, 1), 256>>>(
        (const __half*)pHh, (const __half*)pW1h,
        (const float*)pSc1, (const float*)pSh1, out, 256, 128);
}

// round 14
// speedup vs baseline: 5.3333x; 1.2936x over previous
#include <cuda_runtime.h>
#include <cuda_fp16.h>
#include <cstdint>
#include <cstddef>

#define BB 4
#define NQ 16384
#define MP 4096
#define C1V 128
#define C2V 256
#define D0 256
#define D1 128
#define NTOT (BB*NQ)   // 65536

// ---------------- scratch (device globals; no allocation allowed) ----------------
__device__ float4 g_xyz2p[BB*MP];                  // packed xyz2 + norm
__device__ float  g_sc0[D0], g_sh0[D0], g_sc1[D1], g_sh1[D1];
__device__ float  g_wgt[NTOT*3];
__device__ int    g_idx[NTOT*3];
__device__ int    g_pi[(size_t)NTOT*12];           // 4 tiles x top-3 indices per query
__device__ __half g_A1h[(size_t)NTOT*C1V];         // points1 fp16 (16 MB)
__device__ __half g_A2h[BB*MP*C2V];                // points2 fp16 (8 MB)
__device__ __half g_W0a[256*256];                  // w0[0:256,:]^T  (K-major fp16)
__device__ __half g_W0b[256*128];                  // w0[256:384,:]^T
__device__ __half g_W1h[128*256];                  // w1^T
__device__ __half g_P2Wh[BB*MP*D0];                // points2 @ w0a (8 MB, fp16)
__device__ __half g_G1h[(size_t)NTOT*D0];          // gathered first-layer partial fp16
__device__ __half g_Hh[(size_t)NTOT*D0];           // layer-1 activations fp16

// ---------------- PTX helpers ----------------
__device__ __forceinline__ uint32_t smem_u32(const void* p){
    uint32_t a;
    asm("{ .reg .u64 t; cvta.to.shared.u64 t, %1; cvt.u32.u64 %0, t; }" : "=r"(a) : "l"(p));
    return a;
}
__device__ __forceinline__ void cpa(uint32_t dst, const void* src){
    asm volatile("cp.async.ca.shared.global [%0], [%1], 16;" :: "r"(dst), "l"(src) : "memory");
}
__device__ __forceinline__ void cp_commit(){ asm volatile("cp.async.commit_group;" ::: "memory"); }
template<int NN> __device__ __forceinline__ void cp_wait(){ asm volatile("cp.async.wait_group %0;" :: "n"(NN) : "memory"); }

__device__ __forceinline__ void ldsm4(uint32_t& r0, uint32_t& r1, uint32_t& r2, uint32_t& r3, uint32_t addr){
    asm volatile("ldmatrix.sync.aligned.m8n8.x4.shared.b16 {%0,%1,%2,%3}, [%4];"
        : "=r"(r0), "=r"(r1), "=r"(r2), "=r"(r3) : "r"(addr));
}
__device__ __forceinline__ void mma16816(float* c, const uint32_t* a, const uint32_t* b){
    asm volatile(
        "mma.sync.aligned.m16n8k16.row.col.f32.f16.f16.f32 "
        "{%0,%1,%2,%3}, {%4,%5,%6,%7}, {%8,%9}, {%0,%1,%2,%3};"
        : "+f"(c[0]), "+f"(c[1]), "+f"(c[2]), "+f"(c[3])
        : "r"(a[0]), "r"(a[1]), "r"(a[2]), "r"(a[3]), "r"(b[0]), "r"(b[1]));
}

// ---------------- prep: pack xyz2 (+norm), BN scale/shift ----------------
__global__ void prep_kernel(const float* __restrict__ xyz2,
                            const float* __restrict__ G0, const float* __restrict__ B0,
                            const float* __restrict__ M0, const float* __restrict__ V0,
                            const float* __restrict__ G1, const float* __restrict__ B1,
                            const float* __restrict__ M1, const float* __restrict__ V1)
{
    int i = blockIdx.x*256 + threadIdx.x;
    if (i < BB*MP){
        float x = xyz2[i*3+0], y = xyz2[i*3+1], z = xyz2[i*3+2];
        g_xyz2p[i] = make_float4(x, y, z, x*x + y*y + z*z);
    }
    if (blockIdx.x == 0){
        int t = threadIdx.x;
        if (t < D0){ float s = G0[t]*rsqrtf(V0[t]+1e-3f); g_sc0[t]=s; g_sh0[t]=B0[t]-M0[t]*s; }
        if (t < D1){ float s = G1[t]*rsqrtf(V1[t]+1e-3f); g_sc1[t]=s; g_sh1[t]=B1[t]-M1[t]*s; }
    }
}

// ---------------- fp32 -> fp16 vector convert ----------------
__global__ void __launch_bounds__(256) f2h_kernel(const float4* __restrict__ in, __half2* __restrict__ out){
    int i = blockIdx.x*256 + threadIdx.x;
    float4 v = in[i];
    out[2*i+0] = __floats2half2_rn(v.x, v.y);
    out[2*i+1] = __floats2half2_rn(v.z, v.w);
}

// ---------------- weight transpose + fp16 (K-major for B operand) ----------------
__global__ void __launch_bounds__(256) wtrans_kernel(const float* __restrict__ w0, const float* __restrict__ w1){
    int t = blockIdx.x*256 + threadIdx.x;            // 0..131071
    if (t < 65536){
        int n = t >> 8, k = t & 255;
        g_W0a[n*256 + k] = __float2half_rn(w0[k*256 + n]);
    } else if (t < 98304){
        int u = t - 65536; int n = u >> 7, k = u & 127;  // n<256, k<128
        g_W0b[n*128 + k] = __float2half_rn(w0[(256 + k)*256 + n]);
    } else {
        int u = t - 98304; int n = u >> 8, k = u & 255;  // n<128, k<256
        g_W1h[n*256 + k] = __float2half_rn(w1[k*128 + n]);
    }
}

// ---------------- 3-NN tile pass: scalar loop, 256 queries/block (R10 known-good) ------
__global__ void __launch_bounds__(256) nn3_kernel(const float* __restrict__ xyz1)
{
    __shared__ float4 s[1024];                 // 16 KB
    const int tile = blockIdx.x & 3;
    const int q = (blockIdx.x >> 2)*256 + threadIdx.x;
    const int b = q >> 14;
    const float x = xyz1[q*3+0], y = xyz1[q*3+1], z = xyz1[q*3+2];
    const float ax = -2.f*x, ay = -2.f*y, az = -2.f*z;

    const float4* src = g_xyz2p + b*MP + tile*1024;
    for (int m = threadIdx.x; m < 1024; m += 256) s[m] = src[m];
    __syncthreads();

    float b0v = 3.0e37f, b1v = 3.0e37f, b2v = 3.0e37f;   // shifted space (d2 - n1)
    int   i0 = 0, i1 = 0, i2 = 0;

    #pragma unroll 4
    for (int m = 0; m < 1024; ++m){
        float4 t = s[m];
        float d = fmaf(az, t.z, fmaf(ay, t.y, fmaf(ax, t.x, t.w)));
        if (d < b2v){
            if (d < b1v){
                b2v = b1v; i2 = i1;
                if (d < b0v){ b1v = b0v; i1 = i0; b0v = d; i0 = m; }
                else        { b1v = d;   i1 = m; }
            } else { b2v = d; i2 = m; }
        }
    }

    const int base = tile*1024;
    int* o = g_pi + ((size_t)q*4 + tile)*3;
    o[0] = base + i0; o[1] = base + i1; o[2] = base + i2;
}

// ------- merge: exact-recompute distances of 12 candidates, exact top-3, weights -------
__global__ void __launch_bounds__(256) merge_kernel(const float* __restrict__ xyz1)
{
    const int q = blockIdx.x*256 + threadIdx.x;
    const int b = q >> 14;
    const float x = xyz1[q*3+0], y = xyz1[q*3+1], z = xyz1[q*3+2];
    const float n1 = x*x + y*y + z*z;
    const float ax = -2.f*x, ay = -2.f*y, az = -2.f*z;

    const int* pi = g_pi + (size_t)q*12;

    float b0v = 3.0e37f, b1v = 3.0e37f, b2v = 3.0e37f;
    int   i0 = 0, i1 = 0, i2 = 0;

    #pragma unroll
    for (int c = 0; c < 12; ++c){
        int gm = pi[c];
        float4 t = g_xyz2p[b*MP + gm];
        float d = fmaf(az, t.z, fmaf(ay, t.y, fmaf(ax, t.x, t.w)));
        if (d < b2v){
            if (d < b1v){
                b2v = b1v; i2 = i1;
                if (d < b0v){ b1v = b0v; i1 = i0; b0v = d; i0 = gm; }
                else        { b1v = d;   i1 = gm; }
            } else { b2v = d; i2 = gm; }
        }
    }

    float d0 = fmaxf(n1 + b0v, 1e-10f);
    float d1 = fmaxf(n1 + b1v, 1e-10f);
    float d2 = fmaxf(n1 + b2v, 1e-10f);
    float w0 = 1.f/d0, w1 = 1.f/d1, w2 = 1.f/d2;
    float inv = 1.f/(w0 + w1 + w2);
    g_wgt[q*3+0] = w0*inv; g_wgt[q*3+1] = w1*inv; g_wgt[q*3+2] = w2*inv;
    g_idx[q*3+0] = i0;     g_idx[q*3+1] = i1;     g_idx[q*3+2] = i2;
}

// -------- weighted gather of fp16 P2W rows -> fp16 first-layer partial ----------------
// 32 threads per query; each thread handles 8 halves (uint4).
__global__ void __launch_bounds__(256) gather_kernel()
{
    int t = blockIdx.x*256 + threadIdx.x;     // grid 8192 -> 2M threads
    int q = t >> 5;
    int c = t & 31;                            // chunk of 8 halves
    int b = q >> 14;
    float w0 = g_wgt[q*3+0], w1 = g_wgt[q*3+1], w2 = g_wgt[q*3+2];
    const uint4* P = (const uint4*)g_P2Wh;     // row = 256 halves = 32 uint4
    int base = b * (MP * 32);
    uint4 u0 = P[base + g_idx[q*3+0]*32 + c];
    uint4 u1 = P[base + g_idx[q*3+1]*32 + c];
    uint4 u2 = P[base + g_idx[q*3+2]*32 + c];

    const __half2* h0 = (const __half2*)&u0;
    const __half2* h1 = (const __half2*)&u1;
    const __half2* h2 = (const __half2*)&u2;
    uint4 r;
    __half2* hr = (__half2*)&r;
    #pragma unroll
    for (int k = 0; k < 4; ++k){
        float2 a = __half22float2(h0[k]);
        float2 bb = __half22float2(h1[k]);
        float2 cc = __half22float2(h2[k]);
        float vx = w0*a.x + w1*bb.x + w2*cc.x;
        float vy = w0*a.y + w1*bb.y + w2*cc.y;
        hr[k] = __floats2half2_rn(vx, vy);
    }
    ((uint4*)g_G1h)[(size_t)q*32 + c] = r;
}

// ---------------- fp16 tensor-core GEMM: out = epi(A[M,K]h @ Bt[Nc,K]h^T (+G1h)) ------
// BM=128, BN=128, BK=32, 256 threads (8 warps: 4 along M x 2 along N), double-buffered.
template<bool GATHER, bool BN, bool OUT_HALF>
__global__ void __launch_bounds__(256) gemm_h(
    const __half* __restrict__ A, const __half* __restrict__ Bt,
    const float* __restrict__ scale, const float* __restrict__ shift,
    void* __restrict__ outv, int K, int NcOut)
{
    __shared__ __half As[2][128*40];
    __shared__ __half Bs[2][128*40];

    const int tid  = threadIdx.x;
    const int lane = tid & 31, warp = tid >> 5;
    const int wm = warp & 3, wn = warp >> 2;
    const int mBase = blockIdx.x * 128;
    const int nBase = blockIdx.y * 128;

    float acc[2][8][4];
    #pragma unroll
    for (int mt = 0; mt < 2; ++mt)
        #pragma unroll
        for (int nt = 0; nt < 8; ++nt)
            #pragma unroll
            for (int c = 0; c < 4; ++c) acc[mt][nt][c] = 0.f;

    const uint32_t sA_[2] = { smem_u32(As[0]), smem_u32(As[1]) };
    const uint32_t sB_[2] = { smem_u32(Bs[0]), smem_u32(Bs[1]) };

    const int g  = lane >> 3, lr = lane & 7;
    const uint32_t offA = (uint32_t)((wm*32 + (g&1)*8 + lr)*40 + (g>>1)*8);
    const uint32_t offB = (uint32_t)((wn*64 + (g>>1)*8 + lr)*40 + (g&1)*8);

    const int lrow = tid >> 1;
    const int lseg2 = (tid & 1) * 2;
    const __half* Ag = A + (size_t)(mBase + lrow)*K + lseg2*8;
    const __half* Bg = Bt + (size_t)(nBase + lrow)*K + lseg2*8;
    const uint32_t dA = (uint32_t)(lrow*40 + lseg2*8)*2;
    const uint32_t dB = dA;

    auto load_tile = [&](int kc, int buf){
        const __half* a = Ag + kc*32;
        const __half* b = Bg + kc*32;
        cpa(sA_[buf] + dA,      a);
        cpa(sA_[buf] + dA + 16, a + 8);
        cpa(sB_[buf] + dB,      b);
        cpa(sB_[buf] + dB + 16, b + 8);
        cp_commit();
    };

    const int KC = K >> 5;
    load_tile(0, 0);
    for (int kc = 0; kc < KC; ++kc){
        const int buf = kc & 1;
        if (kc + 1 < KC){ load_tile(kc+1, buf^1); cp_wait<1>(); }
        else            { cp_wait<0>(); }
        __syncthreads();

        const uint32_t sA = sA_[buf], sB = sB_[buf];
        #pragma unroll
        for (int ks = 0; ks < 2; ++ks){
            uint32_t af[2][4];
            uint32_t bf[8][2];
            #pragma unroll
            for (int mt = 0; mt < 2; ++mt)
                ldsm4(af[mt][0], af[mt][1], af[mt][2], af[mt][3],
                      sA + (offA + mt*16*40 + ks*16)*2);
            #pragma unroll
            for (int ntp = 0; ntp < 4; ++ntp)
                ldsm4(bf[2*ntp][0], bf[2*ntp][1], bf[2*ntp+1][0], bf[2*ntp+1][1],
                      sB + (offB + ntp*16*40 + ks*16)*2);
            #pragma unroll
            for (int mt = 0; mt < 2; ++mt)
                #pragma unroll
                for (int nt = 0; nt < 8; ++nt)
                    mma16816(acc[mt][nt], af[mt], bf[nt]);
        }
        __syncthreads();
    }

    #pragma unroll
    for (int mt = 0; mt < 2; ++mt){
        #pragma unroll
        for (int h = 0; h < 2; ++h){
            const int r = mBase + wm*32 + mt*16 + (lane >> 2) + h*8;
            const __half* g1row = GATHER ? (g_G1h + (size_t)r*D0) : nullptr;
            #pragma unroll
            for (int nt = 0; nt < 8; ++nt){
                const int c = nBase + wn*64 + nt*8 + (lane & 3)*2;
                float v0 = acc[mt][nt][h*2+0];
                float v1 = acc[mt][nt][h*2+1];
                if (GATHER){
                    float2 gg = __half22float2(*(const __half2*)(g1row + c));
                    v0 += gg.x; v1 += gg.y;
                }
                if (BN){
                    float2 sc = *(const float2*)(scale + c);
                    float2 sh = *(const float2*)(shift + c);
                    v0 = fmaxf(fmaf(v0, sc.x, sh.x), 0.f);
                    v1 = fmaxf(fmaf(v1, sc.y, sh.y), 0.f);
                }
                if (OUT_HALF){
                    __half2* o = (__half2*)outv;
                    o[((size_t)r*NcOut + c) >> 1] = __floats2half2_rn(v0, v1);
                } else {
                    float2* o = (float2*)outv;
                    o[((size_t)r*NcOut + c) >> 1] = make_float2(v0, v1);
                }
            }
        }
    }
}

// ---------------- launch ----------------
extern "C" void kernel_launch(void* const* d_in, const int* in_sizes, int n_in,
                              void* d_out, int out_size)
{
    const float* xyz1    = (const float*)d_in[0];
    const float* xyz2    = (const float*)d_in[1];
    const float* points1 = (const float*)d_in[2];
    const float* points2 = (const float*)d_in[3];
    const float* w0 = (const float*)d_in[4];
    const float* g0 = (const float*)d_in[5];
    const float* b0 = (const float*)d_in[6];
    const float* m0 = (const float*)d_in[7];
    const float* v0 = (const float*)d_in[8];
    const float* w1 = (const float*)d_in[9];
    const float* g1 = (const float*)d_in[10];
    const float* b1 = (const float*)d_in[11];
    const float* m1 = (const float*)d_in[12];
    const float* v1 = (const float*)d_in[13];
    float* out = (float*)d_out;

    void *pA1h=nullptr, *pA2h=nullptr, *pW0a=nullptr, *pW0b=nullptr, *pW1h=nullptr,
         *pP2Wh=nullptr, *pHh=nullptr, *pSc0=nullptr, *pSh0=nullptr, *pSc1=nullptr, *pSh1=nullptr;
    cudaGetSymbolAddress(&pA1h, g_A1h);
    cudaGetSymbolAddress(&pA2h, g_A2h);
    cudaGetSymbolAddress(&pW0a, g_W0a);
    cudaGetSymbolAddress(&pW0b, g_W0b);
    cudaGetSymbolAddress(&pW1h, g_W1h);
    cudaGetSymbolAddress(&pP2Wh, g_P2Wh);
    cudaGetSymbolAddress(&pHh,  g_Hh);
    cudaGetSymbolAddress(&pSc0, g_sc0);
    cudaGetSymbolAddress(&pSh0, g_sh0);
    cudaGetSymbolAddress(&pSc1, g_sc1);
    cudaGetSymbolAddress(&pSh1, g_sh1);

    // 1) pack xyz2 + BN constants
    prep_kernel<<<64, 256>>>(xyz2, g0, b0, m0, v0, g1, b1, m1, v1);

    // 2) fp16 convert points2
    f2h_kernel<<<BB*MP*C2V/4/256, 256>>>((const float4*)points2, (__half2*)pA2h);

    // 3) weight transpose + fp16
    wtrans_kernel<<<512, 256>>>(w0, w1);

    // 4) P2Wh = points2 @ w0[0:256,:] -> fp16  (M=16384, K=256, N=256)  [PROFILED]
    gemm_h<false,false,true><<<dim3(128, 2), 256>>>(
        (const __half*)pA2h, (const __half*)pW0a, nullptr, nullptr, pP2Wh, 256, 256);

    // 5) 3-NN tile pass
    nn3_kernel<<<1024, 256>>>(xyz1);

    // 6) exact merge -> weights + indices
    merge_kernel<<<256, 256>>>(xyz1);

    // 7) G1h = weighted gather of fp16 P2W rows -> fp16
    gather_kernel<<<8192, 256>>>();

    // 8) fp16 convert points1
    f2h_kernel<<<NTOT*C1V/4/256, 256>>>((const float4*)points1, (__half2*)pA1h);

    // 9) H = relu(bn0(points1 @ w0[256:384,:] + G1h)) -> fp16  (M=65536, K=128, N=256)
    gemm_h<true,true,true><<<dim3(512, 2), 256>>>(
        (const __half*)pA1h, (const __half*)pW0b,
        (const float*)pSc0, (const float*)pSh0, pHh, 128, 256);

    // 10) out = relu(bn1(H @ w1)) -> fp32   (M=65536, K=256, N=128)
    gemm_h<false,true,false><<<dim3(512, 1), 256>>>(
        (const __half*)pHh, (const __half*)pW1h,
        (const float*)pSc1, (const float*)pSh1, out, 256, 128);
}

// round 15
// speedup vs baseline: 5.4624x; 1.0242x over previous
#include <cuda_runtime.h>
#include <cuda_fp16.h>
#include <cstdint>
#include <cstddef>

#define BB 4
#define NQ 16384
#define MP 4096
#define C1V 128
#define C2V 256
#define D0 256
#define D1 128
#define NTOT (BB*NQ)   // 65536

// ---------------- scratch (device globals; no allocation allowed) ----------------
__device__ float4 g_xyz2p[BB*MP];                  // packed xyz2 + norm
__device__ float  g_sc0[D0], g_sh0[D0], g_sc1[D1], g_sh1[D1];
__device__ float  g_wgt[NTOT*3];
__device__ int    g_idx[NTOT*3];
__device__ int    g_pi[(size_t)NTOT*12];           // 4 tiles x top-3 indices per query
__device__ __half g_A1h[(size_t)NTOT*C1V];         // points1 fp16 (16 MB)
__device__ __half g_A2h[BB*MP*C2V];                // points2 fp16 (8 MB)
__device__ __half g_W0a[256*256];                  // w0[0:256,:]^T  (K-major fp16)
__device__ __half g_W0b[256*128];                  // w0[256:384,:]^T
__device__ __half g_W1h[128*256];                  // w1^T
__device__ __half g_P2Wh[BB*MP*D0];                // points2 @ w0a (8 MB, fp16)
__device__ __half g_G1h[(size_t)NTOT*D0];          // gathered first-layer partial fp16
__device__ __half g_Hh[(size_t)NTOT*D0];           // layer-1 activations fp16

// ---------------- PTX helpers ----------------
__device__ __forceinline__ uint32_t smem_u32(const void* p){
    uint32_t a;
    asm("{ .reg .u64 t; cvta.to.shared.u64 t, %1; cvt.u32.u64 %0, t; }" : "=r"(a) : "l"(p));
    return a;
}
__device__ __forceinline__ void cpa(uint32_t dst, const void* src){
    asm volatile("cp.async.ca.shared.global [%0], [%1], 16;" :: "r"(dst), "l"(src) : "memory");
}
__device__ __forceinline__ void cp_commit(){ asm volatile("cp.async.commit_group;" ::: "memory"); }
template<int NN> __device__ __forceinline__ void cp_wait(){ asm volatile("cp.async.wait_group %0;" :: "n"(NN) : "memory"); }

__device__ __forceinline__ void ldsm4(uint32_t& r0, uint32_t& r1, uint32_t& r2, uint32_t& r3, uint32_t addr){
    asm volatile("ldmatrix.sync.aligned.m8n8.x4.shared.b16 {%0,%1,%2,%3}, [%4];"
        : "=r"(r0), "=r"(r1), "=r"(r2), "=r"(r3) : "r"(addr));
}
__device__ __forceinline__ void mma16816(float* c, const uint32_t* a, const uint32_t* b){
    asm volatile(
        "mma.sync.aligned.m16n8k16.row.col.f32.f16.f16.f32 "
        "{%0,%1,%2,%3}, {%4,%5,%6,%7}, {%8,%9}, {%0,%1,%2,%3};"
        : "+f"(c[0]), "+f"(c[1]), "+f"(c[2]), "+f"(c[3])
        : "r"(a[0]), "r"(a[1]), "r"(a[2]), "r"(a[3]), "r"(b[0]), "r"(b[1]));
}

// ---------------- prep: pack xyz2 (+norm), BN scale/shift ----------------
__global__ void prep_kernel(const float* __restrict__ xyz2,
                            const float* __restrict__ G0, const float* __restrict__ B0,
                            const float* __restrict__ M0, const float* __restrict__ V0,
                            const float* __restrict__ G1, const float* __restrict__ B1,
                            const float* __restrict__ M1, const float* __restrict__ V1)
{
    int i = blockIdx.x*256 + threadIdx.x;
    if (i < BB*MP){
        float x = xyz2[i*3+0], y = xyz2[i*3+1], z = xyz2[i*3+2];
        g_xyz2p[i] = make_float4(x, y, z, x*x + y*y + z*z);
    }
    if (blockIdx.x == 0){
        int t = threadIdx.x;
        if (t < D0){ float s = G0[t]*rsqrtf(V0[t]+1e-3f); g_sc0[t]=s; g_sh0[t]=B0[t]-M0[t]*s; }
        if (t < D1){ float s = G1[t]*rsqrtf(V1[t]+1e-3f); g_sc1[t]=s; g_sh1[t]=B1[t]-M1[t]*s; }
    }
}

// ---------------- fp32 -> fp16 vector convert ----------------
__global__ void __launch_bounds__(256) f2h_kernel(const float4* __restrict__ in, __half2* __restrict__ out){
    int i = blockIdx.x*256 + threadIdx.x;
    float4 v = in[i];
    out[2*i+0] = __floats2half2_rn(v.x, v.y);
    out[2*i+1] = __floats2half2_rn(v.z, v.w);
}

// ---------------- weight transpose + fp16 (K-major for B operand) ----------------
__global__ void __launch_bounds__(256) wtrans_kernel(const float* __restrict__ w0, const float* __restrict__ w1){
    int t = blockIdx.x*256 + threadIdx.x;            // 0..131071
    if (t < 65536){
        int n = t >> 8, k = t & 255;
        g_W0a[n*256 + k] = __float2half_rn(w0[k*256 + n]);
    } else if (t < 98304){
        int u = t - 65536; int n = u >> 7, k = u & 127;  // n<256, k<128
        g_W0b[n*128 + k] = __float2half_rn(w0[(256 + k)*256 + n]);
    } else {
        int u = t - 98304; int n = u >> 8, k = u & 255;  // n<128, k<256
        g_W1h[n*256 + k] = __float2half_rn(w1[k*128 + n]);
    }
}

// ---------------- 3-NN tile pass: scalar loop, 256 queries/block (R10 known-good) ------
__global__ void __launch_bounds__(256) nn3_kernel(const float* __restrict__ xyz1)
{
    __shared__ float4 s[1024];                 // 16 KB
    const int tile = blockIdx.x & 3;
    const int q = (blockIdx.x >> 2)*256 + threadIdx.x;
    const int b = q >> 14;
    const float x = xyz1[q*3+0], y = xyz1[q*3+1], z = xyz1[q*3+2];
    const float ax = -2.f*x, ay = -2.f*y, az = -2.f*z;

    const float4* src = g_xyz2p + b*MP + tile*1024;
    for (int m = threadIdx.x; m < 1024; m += 256) s[m] = src[m];
    __syncthreads();

    float b0v = 3.0e37f, b1v = 3.0e37f, b2v = 3.0e37f;   // shifted space (d2 - n1)
    int   i0 = 0, i1 = 0, i2 = 0;

    #pragma unroll 4
    for (int m = 0; m < 1024; ++m){
        float4 t = s[m];
        float d = fmaf(az, t.z, fmaf(ay, t.y, fmaf(ax, t.x, t.w)));
        if (d < b2v){
            if (d < b1v){
                b2v = b1v; i2 = i1;
                if (d < b0v){ b1v = b0v; i1 = i0; b0v = d; i0 = m; }
                else        { b1v = d;   i1 = m; }
            } else { b2v = d; i2 = m; }
        }
    }

    const int base = tile*1024;
    int* o = g_pi + ((size_t)q*4 + tile)*3;
    o[0] = base + i0; o[1] = base + i1; o[2] = base + i2;
}

// ------- merge: exact-recompute distances of 12 candidates, exact top-3, weights -------
__global__ void __launch_bounds__(256) merge_kernel(const float* __restrict__ xyz1)
{
    const int q = blockIdx.x*256 + threadIdx.x;
    const int b = q >> 14;
    const float x = xyz1[q*3+0], y = xyz1[q*3+1], z = xyz1[q*3+2];
    const float n1 = x*x + y*y + z*z;
    const float ax = -2.f*x, ay = -2.f*y, az = -2.f*z;

    const int* pi = g_pi + (size_t)q*12;

    float b0v = 3.0e37f, b1v = 3.0e37f, b2v = 3.0e37f;
    int   i0 = 0, i1 = 0, i2 = 0;

    #pragma unroll
    for (int c = 0; c < 12; ++c){
        int gm = pi[c];
        float4 t = g_xyz2p[b*MP + gm];
        float d = fmaf(az, t.z, fmaf(ay, t.y, fmaf(ax, t.x, t.w)));
        if (d < b2v){
            if (d < b1v){
                b2v = b1v; i2 = i1;
                if (d < b0v){ b1v = b0v; i1 = i0; b0v = d; i0 = gm; }
                else        { b1v = d;   i1 = gm; }
            } else { b2v = d; i2 = gm; }
        }
    }

    float d0 = fmaxf(n1 + b0v, 1e-10f);
    float d1 = fmaxf(n1 + b1v, 1e-10f);
    float d2 = fmaxf(n1 + b2v, 1e-10f);
    float w0 = 1.f/d0, w1 = 1.f/d1, w2 = 1.f/d2;
    float inv = 1.f/(w0 + w1 + w2);
    g_wgt[q*3+0] = w0*inv; g_wgt[q*3+1] = w1*inv; g_wgt[q*3+2] = w2*inv;
    g_idx[q*3+0] = i0;     g_idx[q*3+1] = i1;     g_idx[q*3+2] = i2;
}

// -------- weighted gather of fp16 P2W rows -> fp16 first-layer partial ----------------
__global__ void __launch_bounds__(256) gather_kernel()
{
    int t = blockIdx.x*256 + threadIdx.x;     // grid 8192 -> 2M threads
    int q = t >> 5;
    int c = t & 31;                            // chunk of 8 halves
    int b = q >> 14;
    float w0 = g_wgt[q*3+0], w1 = g_wgt[q*3+1], w2 = g_wgt[q*3+2];
    const uint4* P = (const uint4*)g_P2Wh;     // row = 256 halves = 32 uint4
    int base = b * (MP * 32);
    uint4 u0 = P[base + g_idx[q*3+0]*32 + c];
    uint4 u1 = P[base + g_idx[q*3+1]*32 + c];
    uint4 u2 = P[base + g_idx[q*3+2]*32 + c];

    const __half2* h0 = (const __half2*)&u0;
    const __half2* h1 = (const __half2*)&u1;
    const __half2* h2 = (const __half2*)&u2;
    uint4 r;
    __half2* hr = (__half2*)&r;
    #pragma unroll
    for (int k = 0; k < 4; ++k){
        float2 a = __half22float2(h0[k]);
        float2 bb = __half22float2(h1[k]);
        float2 cc = __half22float2(h2[k]);
        float vx = w0*a.x + w1*bb.x + w2*cc.x;
        float vy = w0*a.y + w1*bb.y + w2*cc.y;
        hr[k] = __floats2half2_rn(vx, vy);
    }
    ((uint4*)g_G1h)[(size_t)q*32 + c] = r;
}

// ---------------- fp16 tensor-core GEMM, 3-stage cp.async pipeline ----------------
// BM=128, BN=128, BK=32, 256 threads (8 warps: 4 along M x 2 along N).
// Dynamic smem: 3 stages x (A 128x40 + B 128x40) halves = 61440 B.
#define STAGE_HALVES (128*40)
#define STAGE_BYTES  (2*STAGE_HALVES*2)

template<bool GATHER, bool BN, bool OUT_HALF>
__global__ void __launch_bounds__(256) gemm_h(
    const __half* __restrict__ A, const __half* __restrict__ Bt,
    const float* __restrict__ scale, const float* __restrict__ shift,
    void* __restrict__ outv, int K, int NcOut)
{
    extern __shared__ __align__(16) __half dsm[];
    const uint32_t sBase = smem_u32(dsm);

    const int tid  = threadIdx.x;
    const int lane = tid & 31, warp = tid >> 5;
    const int wm = warp & 3, wn = warp >> 2;
    const int mBase = blockIdx.x * 128;
    const int nBase = blockIdx.y * 128;

    float acc[2][8][4];
    #pragma unroll
    for (int mt = 0; mt < 2; ++mt)
        #pragma unroll
        for (int nt = 0; nt < 8; ++nt)
            #pragma unroll
            for (int c = 0; c < 4; ++c) acc[mt][nt][c] = 0.f;

    const int g  = lane >> 3, lr = lane & 7;
    const uint32_t offA = (uint32_t)((wm*32 + (g&1)*8 + lr)*40 + (g>>1)*8);
    const uint32_t offB = (uint32_t)((wn*64 + (g>>1)*8 + lr)*40 + (g&1)*8);

    const int lrow = tid >> 1;                 // 0..127
    const int lseg2 = (tid & 1) * 2;           // 0 or 2
    const __half* Ag = A + (size_t)(mBase + lrow)*K + lseg2*8;
    const __half* Bg = Bt + (size_t)(nBase + lrow)*K + lseg2*8;
    const uint32_t dOff = (uint32_t)(lrow*40 + lseg2*8)*2;

    auto load_tile = [&](int kc, int stg){
        const uint32_t sA = sBase + (uint32_t)stg*STAGE_BYTES;
        const uint32_t sB = sA + STAGE_HALVES*2;
        const __half* a = Ag + kc*32;
        const __half* b = Bg + kc*32;
        cpa(sA + dOff,      a);
        cpa(sA + dOff + 16, a + 8);
        cpa(sB + dOff,      b);
        cpa(sB + dOff + 16, b + 8);
        cp_commit();
    };

    const int KC = K >> 5;
    load_tile(0, 0);
    if (KC > 1) load_tile(1, 1);

    int stg = 0;
    for (int kc = 0; kc < KC; ++kc){
        if (kc + 1 < KC) cp_wait<1>(); else cp_wait<0>();
        __syncthreads();

        const uint32_t sA = sBase + (uint32_t)stg*STAGE_BYTES;
        const uint32_t sB = sA + STAGE_HALVES*2;
        #pragma unroll
        for (int ks = 0; ks < 2; ++ks){
            uint32_t af[2][4];
            uint32_t bf[8][2];
            #pragma unroll
            for (int mt = 0; mt < 2; ++mt)
                ldsm4(af[mt][0], af[mt][1], af[mt][2], af[mt][3],
                      sA + (offA + mt*16*40 + ks*16)*2);
            #pragma unroll
            for (int ntp = 0; ntp < 4; ++ntp)
                ldsm4(bf[2*ntp][0], bf[2*ntp][1], bf[2*ntp+1][0], bf[2*ntp+1][1],
                      sB + (offB + ntp*16*40 + ks*16)*2);
            #pragma unroll
            for (int mt = 0; mt < 2; ++mt)
                #pragma unroll
                for (int nt = 0; nt < 8; ++nt)
                    mma16816(acc[mt][nt], af[mt], bf[nt]);
        }

        if (kc + 2 < KC){
            int ns = stg + 2; if (ns >= 3) ns -= 3;
            load_tile(kc + 2, ns);
        }
        if (++stg == 3) stg = 0;
    }

    // ---------------- epilogue ----------------
    #pragma unroll
    for (int mt = 0; mt < 2; ++mt){
        #pragma unroll
        for (int h = 0; h < 2; ++h){
            const int r = mBase + wm*32 + mt*16 + (lane >> 2) + h*8;
            const __half* g1row = GATHER ? (g_G1h + (size_t)r*D0) : nullptr;
            #pragma unroll
            for (int nt = 0; nt < 8; ++nt){
                const int c = nBase + wn*64 + nt*8 + (lane & 3)*2;
                float v0 = acc[mt][nt][h*2+0];
                float v1 = acc[mt][nt][h*2+1];
                if (GATHER){
                    float2 gg = __half22float2(*(const __half2*)(g1row + c));
                    v0 += gg.x; v1 += gg.y;
                }
                if (BN){
                    float2 sc = *(const float2*)(scale + c);
                    float2 sh = *(const float2*)(shift + c);
                    v0 = fmaxf(fmaf(v0, sc.x, sh.x), 0.f);
                    v1 = fmaxf(fmaf(v1, sc.y, sh.y), 0.f);
                }
                if (OUT_HALF){
                    __half2* o = (__half2*)outv;
                    o[((size_t)r*NcOut + c) >> 1] = __floats2half2_rn(v0, v1);
                } else {
                    float2* o = (float2*)outv;
                    o[((size_t)r*NcOut + c) >> 1] = make_float2(v0, v1);
                }
            }
        }
    }
}

#define GEMM_SMEM (3*STAGE_BYTES)   // 61440 bytes

// ---------------- launch ----------------
extern "C" void kernel_launch(void* const* d_in, const int* in_sizes, int n_in,
                              void* d_out, int out_size)
{
    const float* xyz1    = (const float*)d_in[0];
    const float* xyz2    = (const float*)d_in[1];
    const float* points1 = (const float*)d_in[2];
    const float* points2 = (const float*)d_in[3];
    const float* w0 = (const float*)d_in[4];
    const float* g0 = (const float*)d_in[5];
    const float* b0 = (const float*)d_in[6];
    const float* m0 = (const float*)d_in[7];
    const float* v0 = (const float*)d_in[8];
    const float* w1 = (const float*)d_in[9];
    const float* g1 = (const float*)d_in[10];
    const float* b1 = (const float*)d_in[11];
    const float* m1 = (const float*)d_in[12];
    const float* v1 = (const float*)d_in[13];
    float* out = (float*)d_out;

    void *pA1h=nullptr, *pA2h=nullptr, *pW0a=nullptr, *pW0b=nullptr, *pW1h=nullptr,
         *pP2Wh=nullptr, *pHh=nullptr, *pSc0=nullptr, *pSh0=nullptr, *pSc1=nullptr, *pSh1=nullptr;
    cudaGetSymbolAddress(&pA1h, g_A1h);
    cudaGetSymbolAddress(&pA2h, g_A2h);
    cudaGetSymbolAddress(&pW0a, g_W0a);
    cudaGetSymbolAddress(&pW0b, g_W0b);
    cudaGetSymbolAddress(&pW1h, g_W1h);
    cudaGetSymbolAddress(&pP2Wh, g_P2Wh);
    cudaGetSymbolAddress(&pHh,  g_Hh);
    cudaGetSymbolAddress(&pSc0, g_sc0);
    cudaGetSymbolAddress(&pSh0, g_sh0);
    cudaGetSymbolAddress(&pSc1, g_sc1);
    cudaGetSymbolAddress(&pSh1, g_sh1);

    cudaFuncSetAttribute(gemm_h<false,false,true>, cudaFuncAttributeMaxDynamicSharedMemorySize, GEMM_SMEM);
    cudaFuncSetAttribute(gemm_h<true, true, true>, cudaFuncAttributeMaxDynamicSharedMemorySize, GEMM_SMEM);
    cudaFuncSetAttribute(gemm_h<false,true,false>, cudaFuncAttributeMaxDynamicSharedMemorySize, GEMM_SMEM);

    // 1) pack xyz2 + BN constants
    prep_kernel<<<64, 256>>>(xyz2, g0, b0, m0, v0, g1, b1, m1, v1);

    // 2) fp16 convert points2
    f2h_kernel<<<BB*MP*C2V/4/256, 256>>>((const float4*)points2, (__half2*)pA2h);

    // 3) weight transpose + fp16
    wtrans_kernel<<<512, 256>>>(w0, w1);

    // 4) P2Wh = points2 @ w0[0:256,:] -> fp16  (M=16384, K=256, N=256)  [PROFILED]
    gemm_h<false,false,true><<<dim3(128, 2), 256, GEMM_SMEM>>>(
        (const __half*)pA2h, (const __half*)pW0a, nullptr, nullptr, pP2Wh, 256, 256);

    // 5) 3-NN tile pass
    nn3_kernel<<<1024, 256>>>(xyz1);

    // 6) exact merge -> weights + indices
    merge_kernel<<<256, 256>>>(xyz1);

    // 7) G1h = weighted gather of fp16 P2W rows -> fp16
    gather_kernel<<<8192, 256>>>();

    // 8) fp16 convert points1
    f2h_kernel<<<NTOT*C1V/4/256, 256>>>((const float4*)points1, (__half2*)pA1h);

    // 9) H = relu(bn0(points1 @ w0[256:384,:] + G1h)) -> fp16  (M=65536, K=128, N=256)
    gemm_h<true,true,true><<<dim3(512, 2), 256, GEMM_SMEM>>>(
        (const __half*)pA1h, (const __half*)pW0b,
        (const float*)pSc0, (const float*)pSh0, pHh, 128, 256);

    // 10) out = relu(bn1(H @ w1)) -> fp32   (M=65536, K=256, N=128)
    gemm_h<false,true,false><<<dim3(512, 1), 256, GEMM_SMEM>>>(
        (const __half*)pHh, (const __half*)pW1h,
        (const float*)pSc1, (const float*)pSh1, out, 256, 128);
}

// round 16
// speedup vs baseline: 5.6255x; 1.0299x over previous
#include <cuda_runtime.h>
#include <cuda_fp16.h>
#include <cstdint>
#include <cstddef>

#define BB 4
#define NQ 16384
#define MP 4096
#define C1V 128
#define C2V 256
#define D0 256
#define D1 128
#define NTOT (BB*NQ)   // 65536

// ---------------- scratch (device globals; no allocation allowed) ----------------
__device__ float4 g_xyz2p[BB*MP];                  // packed xyz2 + norm
__device__ float  g_sc0[D0], g_sh0[D0], g_sc1[D1], g_sh1[D1];
__device__ float  g_wgt[NTOT*3];
__device__ int    g_idx[NTOT*3];
__device__ int    g_pi[(size_t)NTOT*12];           // 4 tiles x top-3 indices per query
__device__ __half g_A1h[(size_t)NTOT*C1V];         // points1 fp16 (16 MB)
__device__ __half g_A2h[BB*MP*C2V];                // points2 fp16 (8 MB)
__device__ __half g_W0a[256*256];                  // w0[0:256,:]^T  (K-major fp16)
__device__ __half g_W0b[256*128];                  // w0[256:384,:]^T
__device__ __half g_W1h[128*256];                  // w1^T
__device__ __half g_P2Wh[BB*MP*D0];                // points2 @ w0a (8 MB, fp16)
__device__ __half g_G1h[(size_t)NTOT*D0];          // gathered first-layer partial fp16
__device__ __half g_Hh[(size_t)NTOT*D0];           // layer-1 activations fp16

// ---------------- PTX helpers ----------------
__device__ __forceinline__ uint32_t smem_u32(const void* p){
    uint32_t a;
    asm("{ .reg .u64 t; cvta.to.shared.u64 t, %1; cvt.u32.u64 %0, t; }" : "=r"(a) : "l"(p));
    return a;
}
__device__ __forceinline__ void cpa(uint32_t dst, const void* src){
    asm volatile("cp.async.ca.shared.global [%0], [%1], 16;" :: "r"(dst), "l"(src) : "memory");
}
__device__ __forceinline__ void cp_commit(){ asm volatile("cp.async.commit_group;" ::: "memory"); }
template<int NN> __device__ __forceinline__ void cp_wait(){ asm volatile("cp.async.wait_group %0;" :: "n"(NN) : "memory"); }

__device__ __forceinline__ void ldsm4(uint32_t& r0, uint32_t& r1, uint32_t& r2, uint32_t& r3, uint32_t addr){
    asm volatile("ldmatrix.sync.aligned.m8n8.x4.shared.b16 {%0,%1,%2,%3}, [%4];"
        : "=r"(r0), "=r"(r1), "=r"(r2), "=r"(r3) : "r"(addr));
}
__device__ __forceinline__ void mma16816(float* c, const uint32_t* a, const uint32_t* b){
    asm volatile(
        "mma.sync.aligned.m16n8k16.row.col.f32.f16.f16.f32 "
        "{%0,%1,%2,%3}, {%4,%5,%6,%7}, {%8,%9}, {%0,%1,%2,%3};"
        : "+f"(c[0]), "+f"(c[1]), "+f"(c[2]), "+f"(c[3])
        : "r"(a[0]), "r"(a[1]), "r"(a[2]), "r"(a[3]), "r"(b[0]), "r"(b[1]));
}

// ---------------- prep: pack xyz2 (+norm), BN scale/shift ----------------
__global__ void prep_kernel(const float* __restrict__ xyz2,
                            const float* __restrict__ G0, const float* __restrict__ B0,
                            const float* __restrict__ M0, const float* __restrict__ V0,
                            const float* __restrict__ G1, const float* __restrict__ B1,
                            const float* __restrict__ M1, const float* __restrict__ V1)
{
    int i = blockIdx.x*256 + threadIdx.x;
    if (i < BB*MP){
        float x = xyz2[i*3+0], y = xyz2[i*3+1], z = xyz2[i*3+2];
        g_xyz2p[i] = make_float4(x, y, z, x*x + y*y + z*z);
    }
    if (blockIdx.x == 0){
        int t = threadIdx.x;
        if (t < D0){ float s = G0[t]*rsqrtf(V0[t]+1e-3f); g_sc0[t]=s; g_sh0[t]=B0[t]-M0[t]*s; }
        if (t < D1){ float s = G1[t]*rsqrtf(V1[t]+1e-3f); g_sc1[t]=s; g_sh1[t]=B1[t]-M1[t]*s; }
    }
}

// ---------------- fp32 -> fp16 vector convert ----------------
__global__ void __launch_bounds__(256) f2h_kernel(const float4* __restrict__ in, __half2* __restrict__ out){
    int i = blockIdx.x*256 + threadIdx.x;
    float4 v = in[i];
    out[2*i+0] = __floats2half2_rn(v.x, v.y);
    out[2*i+1] = __floats2half2_rn(v.z, v.w);
}

// ---------------- weight transpose + fp16 (K-major for B operand) ----------------
__global__ void __launch_bounds__(256) wtrans_kernel(const float* __restrict__ w0, const float* __restrict__ w1){
    int t = blockIdx.x*256 + threadIdx.x;            // 0..131071
    if (t < 65536){
        int n = t >> 8, k = t & 255;
        g_W0a[n*256 + k] = __float2half_rn(w0[k*256 + n]);
    } else if (t < 98304){
        int u = t - 65536; int n = u >> 7, k = u & 127;  // n<256, k<128
        g_W0b[n*128 + k] = __float2half_rn(w0[(256 + k)*256 + n]);
    } else {
        int u = t - 98304; int n = u >> 8, k = u & 255;  // n<128, k<256
        g_W1h[n*256 + k] = __float2half_rn(w1[k*128 + n]);
    }
}

// ---------------- 3-NN tile pass: scalar loop, 256 queries/block (known-good) ----------
__global__ void __launch_bounds__(256) nn3_kernel(const float* __restrict__ xyz1)
{
    __shared__ float4 s[1024];                 // 16 KB
    const int tile = blockIdx.x & 3;
    const int q = (blockIdx.x >> 2)*256 + threadIdx.x;
    const int b = q >> 14;
    const float x = xyz1[q*3+0], y = xyz1[q*3+1], z = xyz1[q*3+2];
    const float ax = -2.f*x, ay = -2.f*y, az = -2.f*z;

    const float4* src = g_xyz2p + b*MP + tile*1024;
    for (int m = threadIdx.x; m < 1024; m += 256) s[m] = src[m];
    __syncthreads();

    float b0v = 3.0e37f, b1v = 3.0e37f, b2v = 3.0e37f;   // shifted space (d2 - n1)
    int   i0 = 0, i1 = 0, i2 = 0;

    #pragma unroll 4
    for (int m = 0; m < 1024; ++m){
        float4 t = s[m];
        float d = fmaf(az, t.z, fmaf(ay, t.y, fmaf(ax, t.x, t.w)));
        if (d < b2v){
            if (d < b1v){
                b2v = b1v; i2 = i1;
                if (d < b0v){ b1v = b0v; i1 = i0; b0v = d; i0 = m; }
                else        { b1v = d;   i1 = m; }
            } else { b2v = d; i2 = m; }
        }
    }

    const int base = tile*1024;
    int* o = g_pi + ((size_t)q*4 + tile)*3;
    o[0] = base + i0; o[1] = base + i1; o[2] = base + i2;
}

// ------- merge: exact-recompute distances of 12 candidates, exact top-3, weights -------
__global__ void __launch_bounds__(256) merge_kernel(const float* __restrict__ xyz1)
{
    const int q = blockIdx.x*256 + threadIdx.x;
    const int b = q >> 14;
    const float x = xyz1[q*3+0], y = xyz1[q*3+1], z = xyz1[q*3+2];
    const float n1 = x*x + y*y + z*z;
    const float ax = -2.f*x, ay = -2.f*y, az = -2.f*z;

    const int* pi = g_pi + (size_t)q*12;

    float b0v = 3.0e37f, b1v = 3.0e37f, b2v = 3.0e37f;
    int   i0 = 0, i1 = 0, i2 = 0;

    #pragma unroll
    for (int c = 0; c < 12; ++c){
        int gm = pi[c];
        float4 t = g_xyz2p[b*MP + gm];
        float d = fmaf(az, t.z, fmaf(ay, t.y, fmaf(ax, t.x, t.w)));
        if (d < b2v){
            if (d < b1v){
                b2v = b1v; i2 = i1;
                if (d < b0v){ b1v = b0v; i1 = i0; b0v = d; i0 = gm; }
                else        { b1v = d;   i1 = gm; }
            } else { b2v = d; i2 = gm; }
        }
    }

    float d0 = fmaxf(n1 + b0v, 1e-10f);
    float d1 = fmaxf(n1 + b1v, 1e-10f);
    float d2 = fmaxf(n1 + b2v, 1e-10f);
    float w0 = 1.f/d0, w1 = 1.f/d1, w2 = 1.f/d2;
    float inv = 1.f/(w0 + w1 + w2);
    g_wgt[q*3+0] = w0*inv; g_wgt[q*3+1] = w1*inv; g_wgt[q*3+2] = w2*inv;
    g_idx[q*3+0] = i0;     g_idx[q*3+1] = i1;     g_idx[q*3+2] = i2;
}

// -------- weighted gather of fp16 P2W rows -> fp16 first-layer partial ----------------
__global__ void __launch_bounds__(256) gather_kernel()
{
    int t = blockIdx.x*256 + threadIdx.x;     // grid 8192 -> 2M threads
    int q = t >> 5;
    int c = t & 31;                            // chunk of 8 halves
    int b = q >> 14;
    float w0 = g_wgt[q*3+0], w1 = g_wgt[q*3+1], w2 = g_wgt[q*3+2];
    const uint4* P = (const uint4*)g_P2Wh;     // row = 256 halves = 32 uint4
    int base = b * (MP * 32);
    uint4 u0 = P[base + g_idx[q*3+0]*32 + c];
    uint4 u1 = P[base + g_idx[q*3+1]*32 + c];
    uint4 u2 = P[base + g_idx[q*3+2]*32 + c];

    const __half2* h0 = (const __half2*)&u0;
    const __half2* h1 = (const __half2*)&u1;
    const __half2* h2 = (const __half2*)&u2;
    uint4 r;
    __half2* hr = (__half2*)&r;
    #pragma unroll
    for (int k = 0; k < 4; ++k){
        float2 a = __half22float2(h0[k]);
        float2 bb = __half22float2(h1[k]);
        float2 cc = __half22float2(h2[k]);
        float vx = w0*a.x + w1*bb.x + w2*cc.x;
        float vy = w0*a.y + w1*bb.y + w2*cc.y;
        hr[k] = __floats2half2_rn(vx, vy);
    }
    ((uint4*)g_G1h)[(size_t)q*32 + c] = r;
}

// ---------------- fp16 tensor-core GEMM, 3-stage cp.async pipeline ----------------
#define STAGE_HALVES (128*40)
#define STAGE_BYTES  (2*STAGE_HALVES*2)

template<bool GATHER, bool BN, bool OUT_HALF>
__global__ void __launch_bounds__(256) gemm_h(
    const __half* __restrict__ A, const __half* __restrict__ Bt,
    const float* __restrict__ scale, const float* __restrict__ shift,
    void* __restrict__ outv, int K, int NcOut)
{
    extern __shared__ __align__(16) __half dsm[];
    const uint32_t sBase = smem_u32(dsm);

    const int tid  = threadIdx.x;
    const int lane = tid & 31, warp = tid >> 5;
    const int wm = warp & 3, wn = warp >> 2;
    const int mBase = blockIdx.x * 128;
    const int nBase = blockIdx.y * 128;

    float acc[2][8][4];
    #pragma unroll
    for (int mt = 0; mt < 2; ++mt)
        #pragma unroll
        for (int nt = 0; nt < 8; ++nt)
            #pragma unroll
            for (int c = 0; c < 4; ++c) acc[mt][nt][c] = 0.f;

    const int g  = lane >> 3, lr = lane & 7;
    const uint32_t offA = (uint32_t)((wm*32 + (g&1)*8 + lr)*40 + (g>>1)*8);
    const uint32_t offB = (uint32_t)((wn*64 + (g>>1)*8 + lr)*40 + (g&1)*8);

    const int lrow = tid >> 1;                 // 0..127
    const int lseg2 = (tid & 1) * 2;           // 0 or 2
    const __half* Ag = A + (size_t)(mBase + lrow)*K + lseg2*8;
    const __half* Bg = Bt + (size_t)(nBase + lrow)*K + lseg2*8;
    const uint32_t dOff = (uint32_t)(lrow*40 + lseg2*8)*2;

    auto load_tile = [&](int kc, int stg){
        const uint32_t sA = sBase + (uint32_t)stg*STAGE_BYTES;
        const uint32_t sB = sA + STAGE_HALVES*2;
        const __half* a = Ag + kc*32;
        const __half* b = Bg + kc*32;
        cpa(sA + dOff,      a);
        cpa(sA + dOff + 16, a + 8);
        cpa(sB + dOff,      b);
        cpa(sB + dOff + 16, b + 8);
        cp_commit();
    };

    const int KC = K >> 5;
    load_tile(0, 0);
    if (KC > 1) load_tile(1, 1);

    int stg = 0;
    for (int kc = 0; kc < KC; ++kc){
        if (kc + 1 < KC) cp_wait<1>(); else cp_wait<0>();
        __syncthreads();

        const uint32_t sA = sBase + (uint32_t)stg*STAGE_BYTES;
        const uint32_t sB = sA + STAGE_HALVES*2;
        #pragma unroll
        for (int ks = 0; ks < 2; ++ks){
            uint32_t af[2][4];
            uint32_t bf[8][2];
            #pragma unroll
            for (int mt = 0; mt < 2; ++mt)
                ldsm4(af[mt][0], af[mt][1], af[mt][2], af[mt][3],
                      sA + (offA + mt*16*40 + ks*16)*2);
            #pragma unroll
            for (int ntp = 0; ntp < 4; ++ntp)
                ldsm4(bf[2*ntp][0], bf[2*ntp][1], bf[2*ntp+1][0], bf[2*ntp+1][1],
                      sB + (offB + ntp*16*40 + ks*16)*2);
            #pragma unroll
            for (int mt = 0; mt < 2; ++mt)
                #pragma unroll
                for (int nt = 0; nt < 8; ++nt)
                    mma16816(acc[mt][nt], af[mt], bf[nt]);
        }

        if (kc + 2 < KC){
            int ns = stg + 2; if (ns >= 3) ns -= 3;
            load_tile(kc + 2, ns);
        }
        if (++stg == 3) stg = 0;
    }

    // ---------------- epilogue ----------------
    #pragma unroll
    for (int mt = 0; mt < 2; ++mt){
        #pragma unroll
        for (int h = 0; h < 2; ++h){
            const int r = mBase + wm*32 + mt*16 + (lane >> 2) + h*8;
            const __half* g1row = GATHER ? (g_G1h + (size_t)r*D0) : nullptr;
            #pragma unroll
            for (int nt = 0; nt < 8; ++nt){
                const int c = nBase + wn*64 + nt*8 + (lane & 3)*2;
                float v0 = acc[mt][nt][h*2+0];
                float v1 = acc[mt][nt][h*2+1];
                if (GATHER){
                    float2 gg = __half22float2(*(const __half2*)(g1row + c));
                    v0 += gg.x; v1 += gg.y;
                }
                if (BN){
                    float2 sc = *(const float2*)(scale + c);
                    float2 sh = *(const float2*)(shift + c);
                    v0 = fmaxf(fmaf(v0, sc.x, sh.x), 0.f);
                    v1 = fmaxf(fmaf(v1, sc.y, sh.y), 0.f);
                }
                if (OUT_HALF){
                    __half2* o = (__half2*)outv;
                    o[((size_t)r*NcOut + c) >> 1] = __floats2half2_rn(v0, v1);
                } else {
                    float2* o = (float2*)outv;
                    o[((size_t)r*NcOut + c) >> 1] = make_float2(v0, v1);
                }
            }
        }
    }
}

#define GEMM_SMEM (3*STAGE_BYTES)   // 61440 bytes

// ---------------- launch ----------------
extern "C" void kernel_launch(void* const* d_in, const int* in_sizes, int n_in,
                              void* d_out, int out_size)
{
    const float* xyz1    = (const float*)d_in[0];
    const float* xyz2    = (const float*)d_in[1];
    const float* points1 = (const float*)d_in[2];
    const float* points2 = (const float*)d_in[3];
    const float* w0 = (const float*)d_in[4];
    const float* g0 = (const float*)d_in[5];
    const float* b0 = (const float*)d_in[6];
    const float* m0 = (const float*)d_in[7];
    const float* v0 = (const float*)d_in[8];
    const float* w1 = (const float*)d_in[9];
    const float* g1 = (const float*)d_in[10];
    const float* b1 = (const float*)d_in[11];
    const float* m1 = (const float*)d_in[12];
    const float* v1 = (const float*)d_in[13];
    float* out = (float*)d_out;

    void *pA1h=nullptr, *pA2h=nullptr, *pW0a=nullptr, *pW0b=nullptr, *pW1h=nullptr,
         *pP2Wh=nullptr, *pHh=nullptr, *pSc0=nullptr, *pSh0=nullptr, *pSc1=nullptr, *pSh1=nullptr;
    cudaGetSymbolAddress(&pA1h, g_A1h);
    cudaGetSymbolAddress(&pA2h, g_A2h);
    cudaGetSymbolAddress(&pW0a, g_W0a);
    cudaGetSymbolAddress(&pW0b, g_W0b);
    cudaGetSymbolAddress(&pW1h, g_W1h);
    cudaGetSymbolAddress(&pP2Wh, g_P2Wh);
    cudaGetSymbolAddress(&pHh,  g_Hh);
    cudaGetSymbolAddress(&pSc0, g_sc0);
    cudaGetSymbolAddress(&pSh0, g_sh0);
    cudaGetSymbolAddress(&pSc1, g_sc1);
    cudaGetSymbolAddress(&pSh1, g_sh1);

    static cudaStream_t s2 = nullptr;
    static cudaEvent_t evFork = nullptr, evJoin = nullptr;
    if (!s2){
        cudaStreamCreateWithFlags(&s2, cudaStreamNonBlocking);
        cudaEventCreateWithFlags(&evFork, cudaEventDisableTiming);
        cudaEventCreateWithFlags(&evJoin, cudaEventDisableTiming);
        cudaFuncSetAttribute(gemm_h<false,false,true>, cudaFuncAttributeMaxDynamicSharedMemorySize, GEMM_SMEM);
        cudaFuncSetAttribute(gemm_h<true, true, true>, cudaFuncAttributeMaxDynamicSharedMemorySize, GEMM_SMEM);
        cudaFuncSetAttribute(gemm_h<false,true,false>, cudaFuncAttributeMaxDynamicSharedMemorySize, GEMM_SMEM);
    }

    // 1) prep on main stream (needed by both branches)
    prep_kernel<<<64, 256>>>(xyz2, g0, b0, m0, v0, g1, b1, m1, v1);

    // fork: side stream runs the GEMM-branch prologue concurrently with nn3
    cudaEventRecord(evFork, 0);
    cudaStreamWaitEvent(s2, evFork, 0);

    // branch B (stream s2): conversions + weight prep + gemm1
    f2h_kernel<<<BB*MP*C2V/4/256, 256, 0, s2>>>((const float4*)points2, (__half2*)pA2h);
    wtrans_kernel<<<512, 256, 0, s2>>>(w0, w1);
    gemm_h<false,false,true><<<dim3(128, 2), 256, GEMM_SMEM, s2>>>(
        (const __half*)pA2h, (const __half*)pW0a, nullptr, nullptr, pP2Wh, 256, 256);
    f2h_kernel<<<NTOT*C1V/4/256, 256, 0, s2>>>((const float4*)points1, (__half2*)pA1h);
    cudaEventRecord(evJoin, s2);

    // branch A (main stream): 3-NN + merge
    nn3_kernel<<<1024, 256>>>(xyz1);
    merge_kernel<<<256, 256>>>(xyz1);

    // join: gather needs gemm1 (B) + merge (A)
    cudaStreamWaitEvent(0, evJoin, 0);

    // tail (main stream)
    gather_kernel<<<8192, 256>>>();
    gemm_h<true,true,true><<<dim3(512, 2), 256, GEMM_SMEM>>>(
        (const __half*)pA1h, (const __half*)pW0b,
        (const float*)pSc0, (const float*)pSh0, pHh, 128, 256);
    gemm_h<false,true,false><<<dim3(512, 1), 256, GEMM_SMEM>>>(
        (const __half*)pHh, (const __half*)pW1h,
        (const float*)pSc1, (const float*)pSh1, out, 256, 128);
}